// round 15
// baseline (speedup 1.0000x reference)
#include <cuda_runtime.h>
#include <cuda_bf16.h>
#include <math.h>
#include <stdint.h>

// Problem constants
#define TT 2048
#define DD 1024
#define HQ 16
#define HKV 4
#define HD 64
#define EE 8
#define TOPK 2
#define FF 2752
#define NSLOT (TT*TOPK)
#define SCALE 0.125f
#define LB 0.01f

// ---------------- device scratch (no allocs allowed) ----------------
__device__ float g_h[TT*DD];
__device__ float g_q[TT*HQ*HD];
__device__ float g_k[TT*HKV*HD];
__device__ float g_v[TT*HKV*HD];
__device__ float g_attn[TT*HQ*HD];
__device__ __nv_bfloat16 g_h2b[TT*DD];
__device__ int   g_sel[TT*TOPK];
__device__ float g_selw[TT*TOPK];
__device__ int   g_counts[EE];
__device__ int   g_offsets[EE+1];
__device__ int   g_cursor[EE];
__device__ float g_load[EE];
__device__ int   g_slot_tok[NSLOT];
__device__ float g_slot_w[NSLOT];
__device__ __nv_bfloat16 g_actb[(size_t)NSLOT*FF];  // 22.5 MB
// split-KV attention partials
__device__ float g_po0[TT*DD];
__device__ float g_po1[TT*DD];
__device__ float g_pm[2][TT*HQ];
__device__ float g_pl[2][TT*HQ];

// ---------------- helpers ----------------
__device__ __forceinline__ float tf32r(float x) {
    float y;
    asm("cvt.rna.tf32.f32 %0, %1;" : "=f"(y) : "f"(x));
    return y;
}

__device__ __forceinline__ void ldsm4(uint32_t a[4], uint32_t addr) {
    asm volatile("ldmatrix.sync.aligned.m8n8.x4.shared.b16 {%0,%1,%2,%3}, [%4];"
                 : "=r"(a[0]), "=r"(a[1]), "=r"(a[2]), "=r"(a[3]) : "r"(addr));
}

__device__ __forceinline__ void mma8(float d[4], const uint32_t a[4],
                                     uint32_t b0, uint32_t b1) {
    asm volatile(
        "mma.sync.aligned.m16n8k8.row.col.f32.tf32.tf32.f32 "
        "{%0,%1,%2,%3}, {%4,%5,%6,%7}, {%8,%9}, {%0,%1,%2,%3};"
        : "+f"(d[0]), "+f"(d[1]), "+f"(d[2]), "+f"(d[3])
        : "r"(a[0]), "r"(a[1]), "r"(a[2]), "r"(a[3]), "r"(b0), "r"(b1));
}

__device__ __forceinline__ void mma16(float d[4], const uint32_t a[4],
                                      uint32_t b0, uint32_t b1) {
    asm volatile(
        "mma.sync.aligned.m16n8k16.row.col.f32.bf16.bf16.f32 "
        "{%0,%1,%2,%3}, {%4,%5,%6,%7}, {%8,%9}, {%0,%1,%2,%3};"
        : "+f"(d[0]), "+f"(d[1]), "+f"(d[2]), "+f"(d[3])
        : "r"(a[0]), "r"(a[1]), "r"(a[2]), "r"(a[3]), "r"(b0), "r"(b1));
}

__device__ __forceinline__ uint32_t pack_bf2(float lo, float hi) {
    __nv_bfloat16 a = __float2bfloat16(lo), b = __float2bfloat16(hi);
    uint16_t ua = *(uint16_t*)&a, ub = *(uint16_t*)&b;
    return (uint32_t)ua | ((uint32_t)ub << 16);
}

// ---------------- rmsnorm (rmsnorm1 only) ----------------
__global__ void rmsnorm_kernel(const float* __restrict__ x, const float* __restrict__ g,
                               float* __restrict__ out) {
    int t = blockIdx.x;
    const float* xr = x + (size_t)t*DD;
    __shared__ float red[256];
    int tid = threadIdx.x;
    float s = 0.f;
    for (int d = tid; d < DD; d += 256) { float v = xr[d]; s += v*v; }
    red[tid] = s; __syncthreads();
    for (int st = 128; st > 0; st >>= 1) {
        if (tid < st) red[tid] += red[tid+st];
        __syncthreads();
    }
    float inv = rsqrtf(red[0]/(float)DD + 1e-6f);
    float* o = out + (size_t)t*DD;
    for (int d = tid; d < DD; d += 256) o[d] = xr[d]*g[d]*inv;
}

// =====================================================================
// tf32 GEMM (128x64 tile, 8 warps), 2 blocks/SM
// =====================================================================
__global__ __launch_bounds__(256, 2)
void gemm_tf32_kernel(const float* __restrict__ A, const float* __restrict__ B,
                      float* __restrict__ C, int M, int N, int K,
                      const float* __restrict__ res) {
    __shared__ float As_[128][36];
    __shared__ float Bs_[32][72];
    int m0 = blockIdx.y*128, n0 = blockIdx.x*64;
    int tid = threadIdx.x;
    int lane = tid & 31, warp = tid >> 5;
    int m_w = (warp >> 1)*32, n_w = (warp & 1)*32;
    int g = lane >> 2, tg = lane & 3;
    int rr = tid >> 3, cc = tid & 7;

    uint32_t sA = (uint32_t)__cvta_generic_to_shared(&As_[0][0]);

    float acc[2][4][4];
    #pragma unroll
    for (int i = 0; i < 2; i++)
        #pragma unroll
        for (int j = 0; j < 4; j++)
            #pragma unroll
            for (int l = 0; l < 4; l++) acc[i][j][l] = 0.f;

    float4 av[4];
    float bv[8];
    #pragma unroll
    for (int p = 0; p < 4; p++)
        av[p] = *(const float4*)&A[(size_t)(m0 + rr + p*32)*K + cc*4];
    #pragma unroll
    for (int p = 0; p < 8; p++) {
        int idx = p*256 + tid;
        bv[p] = B[(size_t)(idx >> 6)*N + n0 + (idx & 63)];
    }

    for (int k0 = 0; k0 < K; k0 += 32) {
        __syncthreads();
        #pragma unroll
        for (int p = 0; p < 4; p++) {
            float4 v = av[p];
            v.x = tf32r(v.x); v.y = tf32r(v.y); v.z = tf32r(v.z); v.w = tf32r(v.w);
            *(float4*)&As_[rr + p*32][cc*4] = v;
        }
        #pragma unroll
        for (int p = 0; p < 8; p++) {
            int idx = p*256 + tid;
            Bs_[idx >> 6][idx & 63] = tf32r(bv[p]);
        }
        __syncthreads();
        if (k0 + 32 < K) {
            #pragma unroll
            for (int p = 0; p < 4; p++)
                av[p] = *(const float4*)&A[(size_t)(m0 + rr + p*32)*K + k0 + 32 + cc*4];
            #pragma unroll
            for (int p = 0; p < 8; p++) {
                int idx = p*256 + tid;
                bv[p] = B[(size_t)(k0 + 32 + (idx >> 6))*N + n0 + (idx & 63)];
            }
        }
        #pragma unroll
        for (int ks = 0; ks < 4; ks++) {
            uint32_t a0[4], a1[4];
            int acol = ks*8 + ((lane & 16) >> 2);
            int arow = m_w + (lane & 15);
            ldsm4(a0, sA + (uint32_t)(arow*36 + acol)*4u);
            ldsm4(a1, sA + (uint32_t)((arow + 16)*36 + acol)*4u);
            #pragma unroll
            for (int ni = 0; ni < 4; ni++) {
                uint32_t b0 = __float_as_uint(Bs_[ks*8 + tg][n_w + ni*8 + g]);
                uint32_t b1 = __float_as_uint(Bs_[ks*8 + tg + 4][n_w + ni*8 + g]);
                mma8(acc[0][ni], a0, b0, b1);
                mma8(acc[1][ni], a1, b0, b1);
            }
        }
    }

    #pragma unroll
    for (int mi = 0; mi < 2; mi++)
        #pragma unroll
        for (int ni = 0; ni < 4; ni++) {
            int rbase = m0 + m_w + mi*16 + g;
            int c = n0 + n_w + ni*8 + 2*tg;
            #pragma unroll
            for (int hrow = 0; hrow < 2; hrow++) {
                int r = rbase + hrow*8;
                float2 v = make_float2(acc[mi][ni][hrow*2], acc[mi][ni][hrow*2+1]);
                if (res) {
                    float2 rv = *(const float2*)&res[(size_t)r*N + c];
                    v.x += rv.x; v.y += rv.y;
                }
                *(float2*)&C[(size_t)r*N + c] = v;
            }
        }
}

// =====================================================================
// fused QKV projection
// =====================================================================
__global__ __launch_bounds__(256, 2)
void qkv_tf32_kernel(const float* __restrict__ wq, const float* __restrict__ wk,
                     const float* __restrict__ wv) {
    __shared__ float As_[128][36];
    __shared__ float Bs_[32][72];
    int n0g = blockIdx.x*64;
    const float* B; float* C; int N; int n0;
    if (n0g < 1024)      { B = wq; C = g_q; N = HQ*HD;  n0 = n0g; }
    else if (n0g < 1280) { B = wk; C = g_k; N = HKV*HD; n0 = n0g - 1024; }
    else                 { B = wv; C = g_v; N = HKV*HD; n0 = n0g - 1280; }
    const float* A = g_h;
    int m0 = blockIdx.y*128;
    int tid = threadIdx.x;
    int lane = tid & 31, warp = tid >> 5;
    int m_w = (warp >> 1)*32, n_w = (warp & 1)*32;
    int g = lane >> 2, tg = lane & 3;
    int rr = tid >> 3, cc = tid & 7;

    uint32_t sA = (uint32_t)__cvta_generic_to_shared(&As_[0][0]);

    float acc[2][4][4];
    #pragma unroll
    for (int i = 0; i < 2; i++)
        #pragma unroll
        for (int j = 0; j < 4; j++)
            #pragma unroll
            for (int l = 0; l < 4; l++) acc[i][j][l] = 0.f;

    float4 av[4];
    float bv[8];
    #pragma unroll
    for (int p = 0; p < 4; p++)
        av[p] = *(const float4*)&A[(size_t)(m0 + rr + p*32)*DD + cc*4];
    #pragma unroll
    for (int p = 0; p < 8; p++) {
        int idx = p*256 + tid;
        bv[p] = B[(size_t)(idx >> 6)*N + n0 + (idx & 63)];
    }

    for (int k0 = 0; k0 < DD; k0 += 32) {
        __syncthreads();
        #pragma unroll
        for (int p = 0; p < 4; p++) {
            float4 v = av[p];
            v.x = tf32r(v.x); v.y = tf32r(v.y); v.z = tf32r(v.z); v.w = tf32r(v.w);
            *(float4*)&As_[rr + p*32][cc*4] = v;
        }
        #pragma unroll
        for (int p = 0; p < 8; p++) {
            int idx = p*256 + tid;
            Bs_[idx >> 6][idx & 63] = tf32r(bv[p]);
        }
        __syncthreads();
        if (k0 + 32 < DD) {
            #pragma unroll
            for (int p = 0; p < 4; p++)
                av[p] = *(const float4*)&A[(size_t)(m0 + rr + p*32)*DD + k0 + 32 + cc*4];
            #pragma unroll
            for (int p = 0; p < 8; p++) {
                int idx = p*256 + tid;
                bv[p] = B[(size_t)(k0 + 32 + (idx >> 6))*N + n0 + (idx & 63)];
            }
        }
        #pragma unroll
        for (int ks = 0; ks < 4; ks++) {
            uint32_t a0[4], a1[4];
            int acol = ks*8 + ((lane & 16) >> 2);
            int arow = m_w + (lane & 15);
            ldsm4(a0, sA + (uint32_t)(arow*36 + acol)*4u);
            ldsm4(a1, sA + (uint32_t)((arow + 16)*36 + acol)*4u);
            #pragma unroll
            for (int ni = 0; ni < 4; ni++) {
                uint32_t b0 = __float_as_uint(Bs_[ks*8 + tg][n_w + ni*8 + g]);
                uint32_t b1 = __float_as_uint(Bs_[ks*8 + tg + 4][n_w + ni*8 + g]);
                mma8(acc[0][ni], a0, b0, b1);
                mma8(acc[1][ni], a1, b0, b1);
            }
        }
    }

    #pragma unroll
    for (int mi = 0; mi < 2; mi++)
        #pragma unroll
        for (int ni = 0; ni < 4; ni++) {
            int rbase = m0 + m_w + mi*16 + g;
            int c = n0 + n_w + ni*8 + 2*tg;
            #pragma unroll
            for (int hrow = 0; hrow < 2; hrow++) {
                int r = rbase + hrow*8;
                *(float2*)&C[(size_t)r*N + c] =
                    make_float2(acc[mi][ni][hrow*2], acc[mi][ni][hrow*2+1]);
            }
        }
}

// ---------------- RoPE (grid-stride, exp2f freq) ----------------
__global__ void rope_kernel() {
    const int total = TT*(HQ+HKV)*32;
    const float LOG2_10000_32 = 0.4152410118609203f;
    for (int i = blockIdx.x*blockDim.x + threadIdx.x; i < total;
         i += gridDim.x*blockDim.x) {
        int d = i & 31;
        int tmp = i >> 5;
        int hh = tmp % (HQ+HKV);
        int t = tmp / (HQ+HKV);
        float* p;
        if (hh < HQ) p = g_q + (size_t)t*HQ*HD + hh*HD;
        else         p = g_k + (size_t)t*HKV*HD + (hh-HQ)*HD;
        float inv = exp2f(-(float)d * LOG2_10000_32);
        float ang = (float)t * inv;
        float c = cosf(ang), s = sinf(ang);
        float x1 = p[d], x2 = p[d+32];
        p[d]    = x1*c - x2*s;
        p[d+32] = x2*c + x1*s;
    }
}

// =====================================================================
// flash attention tf32, SPLIT-KV
// =====================================================================
#define ATTN_SMEM ((2*64*68 + 64*72)*4)
__global__ __launch_bounds__(128, 3)
void attn_tf32_kernel() {
    extern __shared__ float sm[];
    float* Qs = sm;
    float* KP = sm + 64*68;
    float* Vs = sm + 2*64*68;
    int bx = (int)blockIdx.x >> 1;
    int piece = (int)blockIdx.x & 1;
    int qt = (int)(gridDim.x >> 1) - 1 - bx;
    int mid = (qt + 1) >> 1;
    int kt_lo = piece ? mid : 0;
    int kt_hi = piece ? (qt + 1) : mid;
    int head = blockIdx.y;
    int kvh = head >> 2;
    int qs0 = qt*64;
    int tid = threadIdx.x;
    int lane = tid & 31, warp = tid >> 5;
    int r0 = warp*16;
    int g = lane >> 2, tg = lane & 3;
    uint32_t sQ = (uint32_t)__cvta_generic_to_shared(Qs);
    uint32_t sKP = (uint32_t)__cvta_generic_to_shared(KP);

    #pragma unroll
    for (int it = 0; it < 8; it++) {
        int idx = it*128 + tid;
        int r = idx >> 4, c4 = (idx & 15)*4;
        float4 v = *(const float4*)&g_q[(size_t)(qs0+r)*DD + head*HD + c4];
        v.x = tf32r(v.x); v.y = tf32r(v.y); v.z = tf32r(v.z); v.w = tf32r(v.w);
        *(float4*)&Qs[r*68 + c4] = v;
    }

    float o[8][4];
    #pragma unroll
    for (int ni = 0; ni < 8; ni++)
        #pragma unroll
        for (int j = 0; j < 4; j++) o[ni][j] = 0.f;
    float m0 = -1e30f, m1 = -1e30f, l0 = 0.f, l1 = 0.f;
    int qr0 = qs0 + r0 + g, qr1 = qr0 + 8;

    for (int kt = kt_lo; kt < kt_hi; kt++) {
        __syncthreads();
        #pragma unroll
        for (int it = 0; it < 8; it++) {
            int idx = it*128 + tid;
            int r = idx >> 4, c4 = (idx & 15)*4;
            size_t goff = (size_t)(kt*64+r)*(HKV*HD) + kvh*HD + c4;
            float4 kv = *(const float4*)&g_k[goff];
            kv.x = tf32r(kv.x); kv.y = tf32r(kv.y); kv.z = tf32r(kv.z); kv.w = tf32r(kv.w);
            *(float4*)&KP[r*68 + c4] = kv;
            float4 vv = *(const float4*)&g_v[goff];
            vv.x = tf32r(vv.x); vv.y = tf32r(vv.y); vv.z = tf32r(vv.z); vv.w = tf32r(vv.w);
            *(float4*)&Vs[r*72 + c4] = vv;
        }
        __syncthreads();

        float s[8][4];
        #pragma unroll
        for (int ni = 0; ni < 8; ni++)
            #pragma unroll
            for (int j = 0; j < 4; j++) s[ni][j] = 0.f;
        #pragma unroll
        for (int kc = 0; kc < 8; kc++) {
            uint32_t a[4];
            ldsm4(a, sQ + (uint32_t)((r0 + (lane & 15))*68 + kc*8 + ((lane & 16) >> 2))*4u);
            #pragma unroll
            for (int ni = 0; ni < 8; ni++) {
                uint32_t b0 = __float_as_uint(KP[(ni*8+g)*68 + kc*8 + tg]);
                uint32_t b1 = __float_as_uint(KP[(ni*8+g)*68 + kc*8 + tg + 4]);
                mma8(s[ni], a, b0, b1);
            }
        }
        __syncthreads();

        float tmax0 = -1e30f, tmax1 = -1e30f;
        #pragma unroll
        for (int ni = 0; ni < 8; ni++) {
            #pragma unroll
            for (int j = 0; j < 2; j++) {
                int c = kt*64 + ni*8 + 2*tg + j;
                float v0 = s[ni][j]*SCALE;
                float v1 = s[ni][j+2]*SCALE;
                if (c > qr0) v0 = -1e30f;
                if (c > qr1) v1 = -1e30f;
                s[ni][j] = v0; s[ni][j+2] = v1;
                tmax0 = fmaxf(tmax0, v0); tmax1 = fmaxf(tmax1, v1);
            }
        }
        tmax0 = fmaxf(tmax0, __shfl_xor_sync(0xffffffffu, tmax0, 1));
        tmax0 = fmaxf(tmax0, __shfl_xor_sync(0xffffffffu, tmax0, 2));
        tmax1 = fmaxf(tmax1, __shfl_xor_sync(0xffffffffu, tmax1, 1));
        tmax1 = fmaxf(tmax1, __shfl_xor_sync(0xffffffffu, tmax1, 2));
        float mn0 = fmaxf(m0, tmax0), mn1 = fmaxf(m1, tmax1);
        float a0 = __expf(m0 - mn0), a1 = __expf(m1 - mn1);
        m0 = mn0; m1 = mn1;

        float ls0 = 0.f, ls1 = 0.f;
        #pragma unroll
        for (int ni = 0; ni < 8; ni++) {
            float p0 = __expf(s[ni][0] - m0), p1 = __expf(s[ni][1] - m0);
            float p2 = __expf(s[ni][2] - m1), p3 = __expf(s[ni][3] - m1);
            ls0 += p0 + p1; ls1 += p2 + p3;
            *(float2*)&KP[(r0+g)*68 + ni*8 + 2*tg]   = make_float2(tf32r(p0), tf32r(p1));
            *(float2*)&KP[(r0+g+8)*68 + ni*8 + 2*tg] = make_float2(tf32r(p2), tf32r(p3));
        }
        ls0 += __shfl_xor_sync(0xffffffffu, ls0, 1);
        ls0 += __shfl_xor_sync(0xffffffffu, ls0, 2);
        ls1 += __shfl_xor_sync(0xffffffffu, ls1, 1);
        ls1 += __shfl_xor_sync(0xffffffffu, ls1, 2);
        l0 = l0*a0 + ls0; l1 = l1*a1 + ls1;
        #pragma unroll
        for (int ni = 0; ni < 8; ni++) {
            o[ni][0] *= a0; o[ni][1] *= a0;
            o[ni][2] *= a1; o[ni][3] *= a1;
        }
        __syncwarp();

        #pragma unroll
        for (int kc = 0; kc < 8; kc++) {
            uint32_t a[4];
            ldsm4(a, sKP + (uint32_t)((r0 + (lane & 15))*68 + kc*8 + ((lane & 16) >> 2))*4u);
            #pragma unroll
            for (int ni = 0; ni < 8; ni++) {
                uint32_t b0 = __float_as_uint(Vs[(kc*8+tg)*72 + ni*8 + g]);
                uint32_t b1 = __float_as_uint(Vs[(kc*8+tg+4)*72 + ni*8 + g]);
                mma8(o[ni], a, b0, b1);
            }
        }
    }

    float* PO = piece ? g_po1 : g_po0;
    #pragma unroll
    for (int ni = 0; ni < 8; ni++) {
        *(float2*)&PO[(size_t)qr0*DD + head*HD + ni*8 + 2*tg] =
            make_float2(o[ni][0], o[ni][1]);
        *(float2*)&PO[(size_t)qr1*DD + head*HD + ni*8 + 2*tg] =
            make_float2(o[ni][2], o[ni][3]);
    }
    if (tg == 0) {
        g_pm[piece][qr0*HQ + head] = m0;
        g_pl[piece][qr0*HQ + head] = l0;
        g_pm[piece][qr1*HQ + head] = m1;
        g_pl[piece][qr1*HQ + head] = l1;
    }
}

// ---------------- combine split-KV partials ----------------
__global__ void attn_combine_kernel() {
    int t = blockIdx.x;
    int tid = threadIdx.x;
    #pragma unroll
    for (int i = 0; i < 4; i++) {
        int idx = tid + i*256;
        int head = idx >> 6, d = idx & 63;
        float m0 = g_pm[0][t*HQ + head], m1 = g_pm[1][t*HQ + head];
        float l0 = g_pl[0][t*HQ + head], l1 = g_pl[1][t*HQ + head];
        float m = fmaxf(m0, m1);
        float c0 = __expf(m0 - m), c1 = __expf(m1 - m);
        float l = l0*c0 + l1*c1;
        size_t off = (size_t)t*DD + head*HD + d;
        g_attn[off] = (g_po0[off]*c0 + g_po1[off]*c1) / l;
    }
}

// ---------------- clear counters ----------------
__global__ void clear_kernel() {
    int i = threadIdx.x;
    if (i < EE) { g_counts[i] = 0; g_cursor[i] = 0; g_load[i] = 0.f; }
}

// ---------------- fused rmsnorm2 + gating ----------------
__global__ void rmsnorm_gate_kernel(const float* __restrict__ x, const float* __restrict__ g,
                                    const float* __restrict__ gate_w) {
    int t = blockIdx.x;
    int tid = threadIdx.x;
    int lane = tid & 31, warp = tid >> 5;
    const float* xr = x + (size_t)t*DD;
    __shared__ float red[256];
    float s = 0.f;
    for (int d = tid; d < DD; d += 256) { float v = xr[d]; s += v*v; }
    red[tid] = s; __syncthreads();
    for (int st = 128; st > 0; st >>= 1) {
        if (tid < st) red[tid] += red[tid+st];
        __syncthreads();
    }
    float inv = rsqrtf(red[0]/(float)DD + 1e-6f);

    float acc[EE];
    #pragma unroll
    for (int e = 0; e < EE; e++) acc[e] = 0.f;
    for (int d = tid; d < DD; d += 256) {
        float v = xr[d]*g[d]*inv;
        g_h2b[(size_t)t*DD + d] = __float2bfloat16(v);
        #pragma unroll
        for (int e = 0; e < EE; e++) acc[e] += v*gate_w[d*EE + e];
    }
    #pragma unroll
    for (int e = 0; e < EE; e++) {
        #pragma unroll
        for (int st = 16; st > 0; st >>= 1)
            acc[e] += __shfl_xor_sync(0xffffffffu, acc[e], st);
    }
    __shared__ float part[8][EE];
    if (lane == 0) {
        #pragma unroll
        for (int e = 0; e < EE; e++) part[warp][e] = acc[e];
    }
    __syncthreads();
    if (tid == 0) {
        float p[EE];
        #pragma unroll
        for (int e = 0; e < EE; e++) {
            float v = 0.f;
            #pragma unroll
            for (int w = 0; w < 8; w++) v += part[w][e];
            p[e] = v;
        }
        float mx = p[0];
        for (int e = 1; e < EE; e++) mx = fmaxf(mx, p[e]);
        float ssum = 0.f;
        for (int e = 0; e < EE; e++) { p[e] = __expf(p[e]-mx); ssum += p[e]; }
        for (int e = 0; e < EE; e++) p[e] /= ssum;
        int i0 = 0;
        for (int e = 1; e < EE; e++) if (p[e] > p[i0]) i0 = e;
        int i1 = (i0 == 0) ? 1 : 0;
        for (int e = 0; e < EE; e++) if (e != i0 && p[e] > p[i1]) i1 = e;
        float v0 = p[i0], v1 = p[i1];
        float s2 = v0 + v1 + 1e-8f;
        g_sel[t*2] = i0;   g_selw[t*2] = v0/s2;
        g_sel[t*2+1] = i1; g_selw[t*2+1] = v1/s2;
        atomicAdd(&g_counts[i0], 1);
        atomicAdd(&g_counts[i1], 1);
        for (int e = 0; e < EE; e++) atomicAdd(&g_load[e], p[e]);
    }
}

// ---------------- offsets ----------------
__global__ void offsets_kernel() {
    if (threadIdx.x == 0) {
        int off = 0;
        for (int e = 0; e < EE; e++) { g_offsets[e] = off; off += g_counts[e]; }
        g_offsets[EE] = off;
    }
}

// ---------------- scatter ----------------
__global__ void scatter_kernel() {
    int n = blockIdx.x*256 + threadIdx.x;
    if (n >= TT) return;
    #pragma unroll
    for (int j = 0; j < TOPK; j++) {
        int e = g_sel[n*2+j];
        int pos = g_offsets[e] + atomicAdd(&g_cursor[e], 1);
        g_slot_tok[pos] = n;
        g_slot_w[pos] = g_selw[n*2+j];
    }
}

// =====================================================================
// MoE gate+up GEMM (bf16 m16n8k16), 128-row M tile, silu epilogue
// 8 warps: 4m x 2n (warp tile 32x32). grid(FF/64, NSLOT/128, EE)
// =====================================================================
__global__ __launch_bounds__(256, 2)
void moe_act_bf16(const float* __restrict__ wg, const float* __restrict__ wu) {
    int e = blockIdx.z;
    int ne = g_counts[e];
    int rt = blockIdx.y*128;
    if (rt >= ne) return;
    int start = g_offsets[e];
    int f0 = blockIdx.x*64;

    __shared__ int toks[128];
    __shared__ __nv_bfloat16 Ab[128*40];
    __shared__ uint32_t Bgp[16*72];
    __shared__ uint32_t Bup[16*72];

    int tid = threadIdx.x;
    int lane = tid & 31, warp = tid >> 5;
    int m_w = (warp >> 1)*32, n_w = (warp & 1)*32;
    int g = lane >> 2, tg = lane & 3;
    int arow = tid >> 1, ah = tid & 1;
    int bk = tid >> 6, bn = tid & 63;

    if (tid < 128) {
        int r = rt + tid;
        toks[tid] = g_slot_tok[start + ((r < ne) ? r : (ne - 1))];
    }
    __syncthreads();
    int tokA = toks[arow];

    uint32_t sA = (uint32_t)__cvta_generic_to_shared(&Ab[0]);
    const float* WG = wg + (size_t)e*DD*FF;
    const float* WU = wu + (size_t)e*DD*FF;

    float accg[2][4][4], accu[2][4][4];
    #pragma unroll
    for (int i = 0; i < 2; i++)
        #pragma unroll
        for (int j = 0; j < 4; j++)
            #pragma unroll
            for (int l = 0; l < 4; l++) { accg[i][j][l] = 0.f; accu[i][j][l] = 0.f; }

    uint4 av[2];
    float bg[8], bu[8];
    av[0] = *(const uint4*)&g_h2b[(size_t)tokA*DD + ah*16];
    av[1] = *(const uint4*)&g_h2b[(size_t)tokA*DD + ah*16 + 8];
    #pragma unroll
    for (int p = 0; p < 4; p++) {
        int kp = p*4 + bk;
        size_t off = (size_t)(2*kp)*FF + f0 + bn;
        bg[2*p]   = WG[off];       bg[2*p+1] = WG[off + FF];
        bu[2*p]   = WU[off];       bu[2*p+1] = WU[off + FF];
    }

    for (int k0 = 0; k0 < DD; k0 += 32) {
        __syncthreads();
        *(uint4*)&Ab[arow*40 + ah*16]     = av[0];
        *(uint4*)&Ab[arow*40 + ah*16 + 8] = av[1];
        #pragma unroll
        for (int p = 0; p < 4; p++) {
            int kp = p*4 + bk;
            Bgp[kp*72 + bn] = pack_bf2(bg[2*p], bg[2*p+1]);
            Bup[kp*72 + bn] = pack_bf2(bu[2*p], bu[2*p+1]);
        }
        __syncthreads();
        if (k0 + 32 < DD) {
            av[0] = *(const uint4*)&g_h2b[(size_t)tokA*DD + k0 + 32 + ah*16];
            av[1] = *(const uint4*)&g_h2b[(size_t)tokA*DD + k0 + 32 + ah*16 + 8];
            #pragma unroll
            for (int p = 0; p < 4; p++) {
                int kp = p*4 + bk;
                size_t off = (size_t)(k0 + 32 + 2*kp)*FF + f0 + bn;
                bg[2*p]   = WG[off];  bg[2*p+1] = WG[off + FF];
                bu[2*p]   = WU[off];  bu[2*p+1] = WU[off + FF];
            }
        }
        #pragma unroll
        for (int ks = 0; ks < 2; ks++) {
            uint32_t a0[4], a1[4];
            uint32_t abyte = (uint32_t)(m_w + (lane & 15))*80u + (uint32_t)ks*32u + (lane & 16);
            ldsm4(a0, sA + abyte);
            ldsm4(a1, sA + abyte + 16u*80u);
            #pragma unroll
            for (int ni = 0; ni < 4; ni++) {
                int n = n_w + ni*8 + g;
                uint32_t bg0 = Bgp[(ks*8 + tg)*72 + n];
                uint32_t bg1 = Bgp[(ks*8 + tg + 4)*72 + n];
                uint32_t bu0 = Bup[(ks*8 + tg)*72 + n];
                uint32_t bu1 = Bup[(ks*8 + tg + 4)*72 + n];
                mma16(accg[0][ni], a0, bg0, bg1);
                mma16(accg[1][ni], a1, bg0, bg1);
                mma16(accu[0][ni], a0, bu0, bu1);
                mma16(accu[1][ni], a1, bu0, bu1);
            }
        }
    }

    #pragma unroll
    for (int mi = 0; mi < 2; mi++)
        #pragma unroll
        for (int ni = 0; ni < 4; ni++) {
            int rb = rt + m_w + mi*16 + g;
            int c = f0 + n_w + ni*8 + 2*tg;
            #pragma unroll
            for (int hrow = 0; hrow < 2; hrow++) {
                int r = rb + hrow*8;
                if (r < ne) {
                    float gv0 = accg[mi][ni][hrow*2], gv1 = accg[mi][ni][hrow*2+1];
                    float uv0 = accu[mi][ni][hrow*2], uv1 = accu[mi][ni][hrow*2+1];
                    float ox = (gv0 / (1.f + __expf(-gv0))) * uv0;
                    float oy = (gv1 / (1.f + __expf(-gv1))) * uv1;
                    *(uint32_t*)&g_actb[(size_t)(start + r)*FF + c] = pack_bf2(ox, oy);
                }
            }
        }
}

// =====================================================================
// MoE down GEMM (bf16 m16n8k16), 128x128 tile, atomic scatter epilogue
// 8 warps: 4m x 2n (warp tile 32x64). grid(DD/128, NSLOT/128, EE)
// =====================================================================
__global__ __launch_bounds__(256, 2)
void moe_down_bf16(const float* __restrict__ wd, float* __restrict__ out) {
    int e = blockIdx.z;
    int ne = g_counts[e];
    int rt = blockIdx.y*128;
    if (rt >= ne) return;
    int start = g_offsets[e];
    int n0 = blockIdx.x*128;

    __shared__ __nv_bfloat16 Ab[128*40];
    __shared__ uint32_t Bp[16*136];

    int tid = threadIdx.x;
    int lane = tid & 31, warp = tid >> 5;
    int m_w = (warp >> 1)*32, n_w = (warp & 1)*64;
    int g = lane >> 2, tg = lane & 3;
    int arow = tid >> 1, ah = tid & 1;
    int bk = tid >> 7, bn = tid & 127;

    uint32_t sA = (uint32_t)__cvta_generic_to_shared(&Ab[0]);
    const float* WD = wd + (size_t)e*FF*DD;

    float acc[2][8][4];
    #pragma unroll
    for (int i = 0; i < 2; i++)
        #pragma unroll
        for (int j = 0; j < 8; j++)
            #pragma unroll
            for (int l = 0; l < 4; l++) acc[i][j][l] = 0.f;

    int aslot;
    {
        int ar = start + rt + arow;
        aslot = (ar < NSLOT) ? ar : (NSLOT - 1);
    }

    uint4 av[2];
    float bv[16];
    av[0] = *(const uint4*)&g_actb[(size_t)aslot*FF + ah*16];
    av[1] = *(const uint4*)&g_actb[(size_t)aslot*FF + ah*16 + 8];
    #pragma unroll
    for (int p = 0; p < 8; p++) {
        int kp = p*2 + bk;
        size_t off = (size_t)(2*kp)*DD + n0 + bn;
        bv[2*p]   = WD[off];  bv[2*p+1] = WD[off + DD];
    }

    for (int k0 = 0; k0 < FF; k0 += 32) {
        __syncthreads();
        *(uint4*)&Ab[arow*40 + ah*16]     = av[0];
        *(uint4*)&Ab[arow*40 + ah*16 + 8] = av[1];
        #pragma unroll
        for (int p = 0; p < 8; p++) {
            int kp = p*2 + bk;
            Bp[kp*136 + bn] = pack_bf2(bv[2*p], bv[2*p+1]);
        }
        __syncthreads();
        if (k0 + 32 < FF) {
            av[0] = *(const uint4*)&g_actb[(size_t)aslot*FF + k0 + 32 + ah*16];
            av[1] = *(const uint4*)&g_actb[(size_t)aslot*FF + k0 + 32 + ah*16 + 8];
            #pragma unroll
            for (int p = 0; p < 8; p++) {
                int kp = p*2 + bk;
                size_t off = (size_t)(k0 + 32 + 2*kp)*DD + n0 + bn;
                bv[2*p]   = WD[off];  bv[2*p+1] = WD[off + DD];
            }
        }
        #pragma unroll
        for (int ks = 0; ks < 2; ks++) {
            uint32_t a0[4], a1[4];
            uint32_t abyte = (uint32_t)(m_w + (lane & 15))*80u + (uint32_t)ks*32u + (lane & 16);
            ldsm4(a0, sA + abyte);
            ldsm4(a1, sA + abyte + 16u*80u);
            #pragma unroll
            for (int ni = 0; ni < 8; ni++) {
                int n = n_w + ni*8 + g;
                uint32_t b0 = Bp[(ks*8 + tg)*136 + n];
                uint32_t b1 = Bp[(ks*8 + tg + 4)*136 + n];
                mma16(acc[0][ni], a0, b0, b1);
                mma16(acc[1][ni], a1, b0, b1);
            }
        }
    }

    #pragma unroll
    for (int mi = 0; mi < 2; mi++)
        #pragma unroll
        for (int ni = 0; ni < 8; ni++) {
            int rb = rt + m_w + mi*16 + g;
            int c = n0 + n_w + ni*8 + 2*tg;
            #pragma unroll
            for (int hrow = 0; hrow < 2; hrow++) {
                int r = rb + hrow*8;
                if (r < ne) {
                    int tok = g_slot_tok[start + r];
                    float w = g_slot_w[start + r];
                    atomicAdd(&out[(size_t)tok*DD + c],     w*acc[mi][ni][hrow*2]);
                    atomicAdd(&out[(size_t)tok*DD + c + 1], w*acc[mi][ni][hrow*2+1]);
                }
            }
        }
}

// ---------------- aux loss ----------------
__global__ void aux_kernel(float* __restrict__ out, int out_size) {
    if (threadIdx.x == 0 && out_size > TT*DD) {
        float aux = 0.f;
        for (int e = 0; e < EE; e++) {
            float frac = (float)g_counts[e] / (float)(TT*TOPK);
            float load = g_load[e] / (float)TT;
            aux += frac*load;
        }
        out[TT*DD] = LB * (float)EE * aux;
    }
}

// ---------------- launch ----------------
extern "C" void kernel_launch(void* const* d_in, const int* in_sizes, int n_in,
                              void* d_out, int out_size) {
    const float* x       = (const float*)d_in[0];
    const float* g1      = (const float*)d_in[1];
    const float* g2      = (const float*)d_in[2];
    const float* wq      = (const float*)d_in[3];
    const float* wk      = (const float*)d_in[4];
    const float* wv      = (const float*)d_in[5];
    const float* wo      = (const float*)d_in[6];
    const float* gate_w  = (const float*)d_in[7];
    const float* we_gate = (const float*)d_in[8];
    const float* we_up   = (const float*)d_in[9];
    const float* we_down = (const float*)d_in[10];
    float* out = (float*)d_out;

    static float *p_h = nullptr, *p_attn = nullptr;
    if (!p_h) {
        cudaGetSymbolAddress((void**)&p_h, g_h);
        cudaGetSymbolAddress((void**)&p_attn, g_attn);
        cudaFuncSetAttribute(attn_tf32_kernel, cudaFuncAttributeMaxDynamicSharedMemorySize,
                             ATTN_SMEM);
    }

    clear_kernel<<<1, 32>>>();
    rmsnorm_kernel<<<TT, 256>>>(x, g1, p_h);
    qkv_tf32_kernel<<<dim3(24, TT/128), 256>>>(wq, wk, wv);
    rope_kernel<<<512, 256>>>();
    attn_tf32_kernel<<<dim3(2*TT/64, HQ), 128, ATTN_SMEM>>>();
    attn_combine_kernel<<<TT, 256>>>();
    gemm_tf32_kernel<<<dim3(DD/64, TT/128), 256>>>(p_attn, wo, out, TT, DD, DD, x);
    rmsnorm_gate_kernel<<<TT, 256>>>(out, g2, gate_w);
    offsets_kernel<<<1, 32>>>();
    scatter_kernel<<<(TT+255)/256, 256>>>();
    moe_act_bf16<<<dim3(FF/64, NSLOT/128, EE), 256>>>(we_gate, we_up);
    moe_down_bf16<<<dim3(DD/128, NSLOT/128, EE), 256>>>(we_down, out);
    aux_kernel<<<1, 32>>>(out, out_size);
}

// round 16
// speedup vs baseline: 1.5224x; 1.5224x over previous
#include <cuda_runtime.h>
#include <cuda_bf16.h>
#include <math.h>
#include <stdint.h>

// Problem constants
#define TT 2048
#define DD 1024
#define HQ 16
#define HKV 4
#define HD 64
#define EE 8
#define TOPK 2
#define FF 2752
#define NSLOT (TT*TOPK)
#define SCALE 0.125f
#define LB 0.01f

// ---------------- device scratch (no allocs allowed) ----------------
__device__ float g_h[TT*DD];
__device__ float g_q[TT*HQ*HD];
__device__ float g_k[TT*HKV*HD];
__device__ float g_v[TT*HKV*HD];
__device__ float g_attn[TT*HQ*HD];
__device__ __nv_bfloat16 g_h2b[TT*DD];
__device__ int   g_sel[TT*TOPK];
__device__ float g_selw[TT*TOPK];
__device__ int   g_counts[EE];
__device__ int   g_offsets[EE+1];
__device__ int   g_cursor[EE];
__device__ float g_load[EE];
__device__ int   g_slot_tok[NSLOT];
__device__ float g_slot_w[NSLOT];
__device__ __nv_bfloat16 g_actb[(size_t)NSLOT*FF];  // 22.5 MB
// split-KV attention partials
__device__ float g_po0[TT*DD];
__device__ float g_po1[TT*DD];
__device__ float g_pm[2][TT*HQ];
__device__ float g_pl[2][TT*HQ];

// ---------------- helpers ----------------
__device__ __forceinline__ float tf32r(float x) {
    float y;
    asm("cvt.rna.tf32.f32 %0, %1;" : "=f"(y) : "f"(x));
    return y;
}

__device__ __forceinline__ void ldsm4(uint32_t a[4], uint32_t addr) {
    asm volatile("ldmatrix.sync.aligned.m8n8.x4.shared.b16 {%0,%1,%2,%3}, [%4];"
                 : "=r"(a[0]), "=r"(a[1]), "=r"(a[2]), "=r"(a[3]) : "r"(addr));
}

__device__ __forceinline__ void mma8(float d[4], const uint32_t a[4],
                                     uint32_t b0, uint32_t b1) {
    asm volatile(
        "mma.sync.aligned.m16n8k8.row.col.f32.tf32.tf32.f32 "
        "{%0,%1,%2,%3}, {%4,%5,%6,%7}, {%8,%9}, {%0,%1,%2,%3};"
        : "+f"(d[0]), "+f"(d[1]), "+f"(d[2]), "+f"(d[3])
        : "r"(a[0]), "r"(a[1]), "r"(a[2]), "r"(a[3]), "r"(b0), "r"(b1));
}

__device__ __forceinline__ void mma16(float d[4], const uint32_t a[4],
                                      uint32_t b0, uint32_t b1) {
    asm volatile(
        "mma.sync.aligned.m16n8k16.row.col.f32.bf16.bf16.f32 "
        "{%0,%1,%2,%3}, {%4,%5,%6,%7}, {%8,%9}, {%0,%1,%2,%3};"
        : "+f"(d[0]), "+f"(d[1]), "+f"(d[2]), "+f"(d[3])
        : "r"(a[0]), "r"(a[1]), "r"(a[2]), "r"(a[3]), "r"(b0), "r"(b1));
}

__device__ __forceinline__ uint32_t pack_bf2(float lo, float hi) {
    __nv_bfloat16 a = __float2bfloat16(lo), b = __float2bfloat16(hi);
    uint16_t ua = *(uint16_t*)&a, ub = *(uint16_t*)&b;
    return (uint32_t)ua | ((uint32_t)ub << 16);
}

// ---------------- rmsnorm (rmsnorm1 only) ----------------
__global__ void rmsnorm_kernel(const float* __restrict__ x, const float* __restrict__ g,
                               float* __restrict__ out) {
    int t = blockIdx.x;
    const float* xr = x + (size_t)t*DD;
    __shared__ float red[256];
    int tid = threadIdx.x;
    float s = 0.f;
    for (int d = tid; d < DD; d += 256) { float v = xr[d]; s += v*v; }
    red[tid] = s; __syncthreads();
    for (int st = 128; st > 0; st >>= 1) {
        if (tid < st) red[tid] += red[tid+st];
        __syncthreads();
    }
    float inv = rsqrtf(red[0]/(float)DD + 1e-6f);
    float* o = out + (size_t)t*DD;
    for (int d = tid; d < DD; d += 256) o[d] = xr[d]*g[d]*inv;
}

// =====================================================================
// tf32 GEMM (128x64 tile, 8 warps), 2 blocks/SM
// =====================================================================
__global__ __launch_bounds__(256, 2)
void gemm_tf32_kernel(const float* __restrict__ A, const float* __restrict__ B,
                      float* __restrict__ C, int M, int N, int K,
                      const float* __restrict__ res) {
    __shared__ float As_[128][36];
    __shared__ float Bs_[32][72];
    int m0 = blockIdx.y*128, n0 = blockIdx.x*64;
    int tid = threadIdx.x;
    int lane = tid & 31, warp = tid >> 5;
    int m_w = (warp >> 1)*32, n_w = (warp & 1)*32;
    int g = lane >> 2, tg = lane & 3;
    int rr = tid >> 3, cc = tid & 7;

    uint32_t sA = (uint32_t)__cvta_generic_to_shared(&As_[0][0]);

    float acc[2][4][4];
    #pragma unroll
    for (int i = 0; i < 2; i++)
        #pragma unroll
        for (int j = 0; j < 4; j++)
            #pragma unroll
            for (int l = 0; l < 4; l++) acc[i][j][l] = 0.f;

    float4 av[4];
    float bv[8];
    #pragma unroll
    for (int p = 0; p < 4; p++)
        av[p] = *(const float4*)&A[(size_t)(m0 + rr + p*32)*K + cc*4];
    #pragma unroll
    for (int p = 0; p < 8; p++) {
        int idx = p*256 + tid;
        bv[p] = B[(size_t)(idx >> 6)*N + n0 + (idx & 63)];
    }

    for (int k0 = 0; k0 < K; k0 += 32) {
        __syncthreads();
        #pragma unroll
        for (int p = 0; p < 4; p++) {
            float4 v = av[p];
            v.x = tf32r(v.x); v.y = tf32r(v.y); v.z = tf32r(v.z); v.w = tf32r(v.w);
            *(float4*)&As_[rr + p*32][cc*4] = v;
        }
        #pragma unroll
        for (int p = 0; p < 8; p++) {
            int idx = p*256 + tid;
            Bs_[idx >> 6][idx & 63] = tf32r(bv[p]);
        }
        __syncthreads();
        if (k0 + 32 < K) {
            #pragma unroll
            for (int p = 0; p < 4; p++)
                av[p] = *(const float4*)&A[(size_t)(m0 + rr + p*32)*K + k0 + 32 + cc*4];
            #pragma unroll
            for (int p = 0; p < 8; p++) {
                int idx = p*256 + tid;
                bv[p] = B[(size_t)(k0 + 32 + (idx >> 6))*N + n0 + (idx & 63)];
            }
        }
        #pragma unroll
        for (int ks = 0; ks < 4; ks++) {
            uint32_t a0[4], a1[4];
            int acol = ks*8 + ((lane & 16) >> 2);
            int arow = m_w + (lane & 15);
            ldsm4(a0, sA + (uint32_t)(arow*36 + acol)*4u);
            ldsm4(a1, sA + (uint32_t)((arow + 16)*36 + acol)*4u);
            #pragma unroll
            for (int ni = 0; ni < 4; ni++) {
                uint32_t b0 = __float_as_uint(Bs_[ks*8 + tg][n_w + ni*8 + g]);
                uint32_t b1 = __float_as_uint(Bs_[ks*8 + tg + 4][n_w + ni*8 + g]);
                mma8(acc[0][ni], a0, b0, b1);
                mma8(acc[1][ni], a1, b0, b1);
            }
        }
    }

    #pragma unroll
    for (int mi = 0; mi < 2; mi++)
        #pragma unroll
        for (int ni = 0; ni < 4; ni++) {
            int rbase = m0 + m_w + mi*16 + g;
            int c = n0 + n_w + ni*8 + 2*tg;
            #pragma unroll
            for (int hrow = 0; hrow < 2; hrow++) {
                int r = rbase + hrow*8;
                float2 v = make_float2(acc[mi][ni][hrow*2], acc[mi][ni][hrow*2+1]);
                if (res) {
                    float2 rv = *(const float2*)&res[(size_t)r*N + c];
                    v.x += rv.x; v.y += rv.y;
                }
                *(float2*)&C[(size_t)r*N + c] = v;
            }
        }
}

// =====================================================================
// fused QKV projection
// =====================================================================
__global__ __launch_bounds__(256, 2)
void qkv_tf32_kernel(const float* __restrict__ wq, const float* __restrict__ wk,
                     const float* __restrict__ wv) {
    __shared__ float As_[128][36];
    __shared__ float Bs_[32][72];
    int n0g = blockIdx.x*64;
    const float* B; float* C; int N; int n0;
    if (n0g < 1024)      { B = wq; C = g_q; N = HQ*HD;  n0 = n0g; }
    else if (n0g < 1280) { B = wk; C = g_k; N = HKV*HD; n0 = n0g - 1024; }
    else                 { B = wv; C = g_v; N = HKV*HD; n0 = n0g - 1280; }
    const float* A = g_h;
    int m0 = blockIdx.y*128;
    int tid = threadIdx.x;
    int lane = tid & 31, warp = tid >> 5;
    int m_w = (warp >> 1)*32, n_w = (warp & 1)*32;
    int g = lane >> 2, tg = lane & 3;
    int rr = tid >> 3, cc = tid & 7;

    uint32_t sA = (uint32_t)__cvta_generic_to_shared(&As_[0][0]);

    float acc[2][4][4];
    #pragma unroll
    for (int i = 0; i < 2; i++)
        #pragma unroll
        for (int j = 0; j < 4; j++)
            #pragma unroll
            for (int l = 0; l < 4; l++) acc[i][j][l] = 0.f;

    float4 av[4];
    float bv[8];
    #pragma unroll
    for (int p = 0; p < 4; p++)
        av[p] = *(const float4*)&A[(size_t)(m0 + rr + p*32)*DD + cc*4];
    #pragma unroll
    for (int p = 0; p < 8; p++) {
        int idx = p*256 + tid;
        bv[p] = B[(size_t)(idx >> 6)*N + n0 + (idx & 63)];
    }

    for (int k0 = 0; k0 < DD; k0 += 32) {
        __syncthreads();
        #pragma unroll
        for (int p = 0; p < 4; p++) {
            float4 v = av[p];
            v.x = tf32r(v.x); v.y = tf32r(v.y); v.z = tf32r(v.z); v.w = tf32r(v.w);
            *(float4*)&As_[rr + p*32][cc*4] = v;
        }
        #pragma unroll
        for (int p = 0; p < 8; p++) {
            int idx = p*256 + tid;
            Bs_[idx >> 6][idx & 63] = tf32r(bv[p]);
        }
        __syncthreads();
        if (k0 + 32 < DD) {
            #pragma unroll
            for (int p = 0; p < 4; p++)
                av[p] = *(const float4*)&A[(size_t)(m0 + rr + p*32)*DD + k0 + 32 + cc*4];
            #pragma unroll
            for (int p = 0; p < 8; p++) {
                int idx = p*256 + tid;
                bv[p] = B[(size_t)(k0 + 32 + (idx >> 6))*N + n0 + (idx & 63)];
            }
        }
        #pragma unroll
        for (int ks = 0; ks < 4; ks++) {
            uint32_t a0[4], a1[4];
            int acol = ks*8 + ((lane & 16) >> 2);
            int arow = m_w + (lane & 15);
            ldsm4(a0, sA + (uint32_t)(arow*36 + acol)*4u);
            ldsm4(a1, sA + (uint32_t)((arow + 16)*36 + acol)*4u);
            #pragma unroll
            for (int ni = 0; ni < 4; ni++) {
                uint32_t b0 = __float_as_uint(Bs_[ks*8 + tg][n_w + ni*8 + g]);
                uint32_t b1 = __float_as_uint(Bs_[ks*8 + tg + 4][n_w + ni*8 + g]);
                mma8(acc[0][ni], a0, b0, b1);
                mma8(acc[1][ni], a1, b0, b1);
            }
        }
    }

    #pragma unroll
    for (int mi = 0; mi < 2; mi++)
        #pragma unroll
        for (int ni = 0; ni < 4; ni++) {
            int rbase = m0 + m_w + mi*16 + g;
            int c = n0 + n_w + ni*8 + 2*tg;
            #pragma unroll
            for (int hrow = 0; hrow < 2; hrow++) {
                int r = rbase + hrow*8;
                *(float2*)&C[(size_t)r*N + c] =
                    make_float2(acc[mi][ni][hrow*2], acc[mi][ni][hrow*2+1]);
            }
        }
}

// ---------------- RoPE (grid-stride, exp2f freq) ----------------
__global__ void rope_kernel() {
    const int total = TT*(HQ+HKV)*32;
    const float LOG2_10000_32 = 0.4152410118609203f;
    for (int i = blockIdx.x*blockDim.x + threadIdx.x; i < total;
         i += gridDim.x*blockDim.x) {
        int d = i & 31;
        int tmp = i >> 5;
        int hh = tmp % (HQ+HKV);
        int t = tmp / (HQ+HKV);
        float* p;
        if (hh < HQ) p = g_q + (size_t)t*HQ*HD + hh*HD;
        else         p = g_k + (size_t)t*HKV*HD + (hh-HQ)*HD;
        float inv = exp2f(-(float)d * LOG2_10000_32);
        float ang = (float)t * inv;
        float c = cosf(ang), s = sinf(ang);
        float x1 = p[d], x2 = p[d+32];
        p[d]    = x1*c - x2*s;
        p[d+32] = x2*c + x1*s;
    }
}

// =====================================================================
// flash attention tf32, SPLIT-KV
// =====================================================================
#define ATTN_SMEM ((2*64*68 + 64*72)*4)
__global__ __launch_bounds__(128, 3)
void attn_tf32_kernel() {
    extern __shared__ float sm[];
    float* Qs = sm;
    float* KP = sm + 64*68;
    float* Vs = sm + 2*64*68;
    int bx = (int)blockIdx.x >> 1;
    int piece = (int)blockIdx.x & 1;
    int qt = (int)(gridDim.x >> 1) - 1 - bx;
    int mid = (qt + 1) >> 1;
    int kt_lo = piece ? mid : 0;
    int kt_hi = piece ? (qt + 1) : mid;
    int head = blockIdx.y;
    int kvh = head >> 2;
    int qs0 = qt*64;
    int tid = threadIdx.x;
    int lane = tid & 31, warp = tid >> 5;
    int r0 = warp*16;
    int g = lane >> 2, tg = lane & 3;
    uint32_t sQ = (uint32_t)__cvta_generic_to_shared(Qs);
    uint32_t sKP = (uint32_t)__cvta_generic_to_shared(KP);

    #pragma unroll
    for (int it = 0; it < 8; it++) {
        int idx = it*128 + tid;
        int r = idx >> 4, c4 = (idx & 15)*4;
        float4 v = *(const float4*)&g_q[(size_t)(qs0+r)*DD + head*HD + c4];
        v.x = tf32r(v.x); v.y = tf32r(v.y); v.z = tf32r(v.z); v.w = tf32r(v.w);
        *(float4*)&Qs[r*68 + c4] = v;
    }

    float o[8][4];
    #pragma unroll
    for (int ni = 0; ni < 8; ni++)
        #pragma unroll
        for (int j = 0; j < 4; j++) o[ni][j] = 0.f;
    float m0 = -1e30f, m1 = -1e30f, l0 = 0.f, l1 = 0.f;
    int qr0 = qs0 + r0 + g, qr1 = qr0 + 8;

    for (int kt = kt_lo; kt < kt_hi; kt++) {
        __syncthreads();
        #pragma unroll
        for (int it = 0; it < 8; it++) {
            int idx = it*128 + tid;
            int r = idx >> 4, c4 = (idx & 15)*4;
            size_t goff = (size_t)(kt*64+r)*(HKV*HD) + kvh*HD + c4;
            float4 kv = *(const float4*)&g_k[goff];
            kv.x = tf32r(kv.x); kv.y = tf32r(kv.y); kv.z = tf32r(kv.z); kv.w = tf32r(kv.w);
            *(float4*)&KP[r*68 + c4] = kv;
            float4 vv = *(const float4*)&g_v[goff];
            vv.x = tf32r(vv.x); vv.y = tf32r(vv.y); vv.z = tf32r(vv.z); vv.w = tf32r(vv.w);
            *(float4*)&Vs[r*72 + c4] = vv;
        }
        __syncthreads();

        float s[8][4];
        #pragma unroll
        for (int ni = 0; ni < 8; ni++)
            #pragma unroll
            for (int j = 0; j < 4; j++) s[ni][j] = 0.f;
        #pragma unroll
        for (int kc = 0; kc < 8; kc++) {
            uint32_t a[4];
            ldsm4(a, sQ + (uint32_t)((r0 + (lane & 15))*68 + kc*8 + ((lane & 16) >> 2))*4u);
            #pragma unroll
            for (int ni = 0; ni < 8; ni++) {
                uint32_t b0 = __float_as_uint(KP[(ni*8+g)*68 + kc*8 + tg]);
                uint32_t b1 = __float_as_uint(KP[(ni*8+g)*68 + kc*8 + tg + 4]);
                mma8(s[ni], a, b0, b1);
            }
        }
        __syncthreads();

        float tmax0 = -1e30f, tmax1 = -1e30f;
        #pragma unroll
        for (int ni = 0; ni < 8; ni++) {
            #pragma unroll
            for (int j = 0; j < 2; j++) {
                int c = kt*64 + ni*8 + 2*tg + j;
                float v0 = s[ni][j]*SCALE;
                float v1 = s[ni][j+2]*SCALE;
                if (c > qr0) v0 = -1e30f;
                if (c > qr1) v1 = -1e30f;
                s[ni][j] = v0; s[ni][j+2] = v1;
                tmax0 = fmaxf(tmax0, v0); tmax1 = fmaxf(tmax1, v1);
            }
        }
        tmax0 = fmaxf(tmax0, __shfl_xor_sync(0xffffffffu, tmax0, 1));
        tmax0 = fmaxf(tmax0, __shfl_xor_sync(0xffffffffu, tmax0, 2));
        tmax1 = fmaxf(tmax1, __shfl_xor_sync(0xffffffffu, tmax1, 1));
        tmax1 = fmaxf(tmax1, __shfl_xor_sync(0xffffffffu, tmax1, 2));
        float mn0 = fmaxf(m0, tmax0), mn1 = fmaxf(m1, tmax1);
        float a0 = __expf(m0 - mn0), a1 = __expf(m1 - mn1);
        m0 = mn0; m1 = mn1;

        float ls0 = 0.f, ls1 = 0.f;
        #pragma unroll
        for (int ni = 0; ni < 8; ni++) {
            float p0 = __expf(s[ni][0] - m0), p1 = __expf(s[ni][1] - m0);
            float p2 = __expf(s[ni][2] - m1), p3 = __expf(s[ni][3] - m1);
            ls0 += p0 + p1; ls1 += p2 + p3;
            *(float2*)&KP[(r0+g)*68 + ni*8 + 2*tg]   = make_float2(tf32r(p0), tf32r(p1));
            *(float2*)&KP[(r0+g+8)*68 + ni*8 + 2*tg] = make_float2(tf32r(p2), tf32r(p3));
        }
        ls0 += __shfl_xor_sync(0xffffffffu, ls0, 1);
        ls0 += __shfl_xor_sync(0xffffffffu, ls0, 2);
        ls1 += __shfl_xor_sync(0xffffffffu, ls1, 1);
        ls1 += __shfl_xor_sync(0xffffffffu, ls1, 2);
        l0 = l0*a0 + ls0; l1 = l1*a1 + ls1;
        #pragma unroll
        for (int ni = 0; ni < 8; ni++) {
            o[ni][0] *= a0; o[ni][1] *= a0;
            o[ni][2] *= a1; o[ni][3] *= a1;
        }
        __syncwarp();

        #pragma unroll
        for (int kc = 0; kc < 8; kc++) {
            uint32_t a[4];
            ldsm4(a, sKP + (uint32_t)((r0 + (lane & 15))*68 + kc*8 + ((lane & 16) >> 2))*4u);
            #pragma unroll
            for (int ni = 0; ni < 8; ni++) {
                uint32_t b0 = __float_as_uint(Vs[(kc*8+tg)*72 + ni*8 + g]);
                uint32_t b1 = __float_as_uint(Vs[(kc*8+tg+4)*72 + ni*8 + g]);
                mma8(o[ni], a, b0, b1);
            }
        }
    }

    float* PO = piece ? g_po1 : g_po0;
    #pragma unroll
    for (int ni = 0; ni < 8; ni++) {
        *(float2*)&PO[(size_t)qr0*DD + head*HD + ni*8 + 2*tg] =
            make_float2(o[ni][0], o[ni][1]);
        *(float2*)&PO[(size_t)qr1*DD + head*HD + ni*8 + 2*tg] =
            make_float2(o[ni][2], o[ni][3]);
    }
    if (tg == 0) {
        g_pm[piece][qr0*HQ + head] = m0;
        g_pl[piece][qr0*HQ + head] = l0;
        g_pm[piece][qr1*HQ + head] = m1;
        g_pl[piece][qr1*HQ + head] = l1;
    }
}

// ---------------- combine split-KV partials ----------------
__global__ void attn_combine_kernel() {
    int t = blockIdx.x;
    int tid = threadIdx.x;
    #pragma unroll
    for (int i = 0; i < 4; i++) {
        int idx = tid + i*256;
        int head = idx >> 6, d = idx & 63;
        float m0 = g_pm[0][t*HQ + head], m1 = g_pm[1][t*HQ + head];
        float l0 = g_pl[0][t*HQ + head], l1 = g_pl[1][t*HQ + head];
        float m = fmaxf(m0, m1);
        float c0 = __expf(m0 - m), c1 = __expf(m1 - m);
        float l = l0*c0 + l1*c1;
        size_t off = (size_t)t*DD + head*HD + d;
        g_attn[off] = (g_po0[off]*c0 + g_po1[off]*c1) / l;
    }
}

// ---------------- clear counters ----------------
__global__ void clear_kernel() {
    int i = threadIdx.x;
    if (i < EE) { g_counts[i] = 0; g_cursor[i] = 0; g_load[i] = 0.f; }
}

// ---------------- fused rmsnorm2 + gating ----------------
__global__ void rmsnorm_gate_kernel(const float* __restrict__ x, const float* __restrict__ g,
                                    const float* __restrict__ gate_w) {
    int t = blockIdx.x;
    int tid = threadIdx.x;
    int lane = tid & 31, warp = tid >> 5;
    const float* xr = x + (size_t)t*DD;
    __shared__ float red[256];
    float s = 0.f;
    for (int d = tid; d < DD; d += 256) { float v = xr[d]; s += v*v; }
    red[tid] = s; __syncthreads();
    for (int st = 128; st > 0; st >>= 1) {
        if (tid < st) red[tid] += red[tid+st];
        __syncthreads();
    }
    float inv = rsqrtf(red[0]/(float)DD + 1e-6f);

    float acc[EE];
    #pragma unroll
    for (int e = 0; e < EE; e++) acc[e] = 0.f;
    for (int d = tid; d < DD; d += 256) {
        float v = xr[d]*g[d]*inv;
        g_h2b[(size_t)t*DD + d] = __float2bfloat16(v);
        #pragma unroll
        for (int e = 0; e < EE; e++) acc[e] += v*gate_w[d*EE + e];
    }
    #pragma unroll
    for (int e = 0; e < EE; e++) {
        #pragma unroll
        for (int st = 16; st > 0; st >>= 1)
            acc[e] += __shfl_xor_sync(0xffffffffu, acc[e], st);
    }
    __shared__ float part[8][EE];
    if (lane == 0) {
        #pragma unroll
        for (int e = 0; e < EE; e++) part[warp][e] = acc[e];
    }
    __syncthreads();
    if (tid == 0) {
        float p[EE];
        #pragma unroll
        for (int e = 0; e < EE; e++) {
            float v = 0.f;
            #pragma unroll
            for (int w = 0; w < 8; w++) v += part[w][e];
            p[e] = v;
        }
        float mx = p[0];
        for (int e = 1; e < EE; e++) mx = fmaxf(mx, p[e]);
        float ssum = 0.f;
        for (int e = 0; e < EE; e++) { p[e] = __expf(p[e]-mx); ssum += p[e]; }
        for (int e = 0; e < EE; e++) p[e] /= ssum;
        int i0 = 0;
        for (int e = 1; e < EE; e++) if (p[e] > p[i0]) i0 = e;
        int i1 = (i0 == 0) ? 1 : 0;
        for (int e = 0; e < EE; e++) if (e != i0 && p[e] > p[i1]) i1 = e;
        float v0 = p[i0], v1 = p[i1];
        float s2 = v0 + v1 + 1e-8f;
        g_sel[t*2] = i0;   g_selw[t*2] = v0/s2;
        g_sel[t*2+1] = i1; g_selw[t*2+1] = v1/s2;
        atomicAdd(&g_counts[i0], 1);
        atomicAdd(&g_counts[i1], 1);
        for (int e = 0; e < EE; e++) atomicAdd(&g_load[e], p[e]);
    }
}

// ---------------- fused offsets + scatter (single block) ----------------
__global__ void route_kernel() {
    if (threadIdx.x == 0) {
        int off = 0;
        for (int e = 0; e < EE; e++) { g_offsets[e] = off; off += g_counts[e]; }
        g_offsets[EE] = off;
    }
    __syncthreads();
    for (int n = threadIdx.x; n < TT; n += blockDim.x) {
        #pragma unroll
        for (int j = 0; j < TOPK; j++) {
            int e = g_sel[n*2+j];
            int pos = g_offsets[e] + atomicAdd(&g_cursor[e], 1);
            g_slot_tok[pos] = n;
            g_slot_w[pos] = g_selw[n*2+j];
        }
    }
}

// =====================================================================
// MoE gate+up GEMM (bf16 m16n8k16), 128-row M tile, silu epilogue
// DOUBLE-BUFFERED smem pipeline: one __syncthreads per k-tile.
// 8 warps: 4m x 2n (warp tile 32x32). grid(FF/64, NSLOT/128, EE)
// =====================================================================
__global__ __launch_bounds__(256, 2)
void moe_act_bf16(const float* __restrict__ wg, const float* __restrict__ wu) {
    int e = blockIdx.z;
    int ne = g_counts[e];
    int rt = blockIdx.y*128;
    if (rt >= ne) return;
    int start = g_offsets[e];
    int f0 = blockIdx.x*64;

    __shared__ int toks[128];
    __shared__ __nv_bfloat16 Ab[2][128*40];
    __shared__ uint32_t Bgp[2][16*72];
    __shared__ uint32_t Bup[2][16*72];

    int tid = threadIdx.x;
    int lane = tid & 31, warp = tid >> 5;
    int m_w = (warp >> 1)*32, n_w = (warp & 1)*32;
    int g = lane >> 2, tg = lane & 3;
    int arow = tid >> 1, ah = tid & 1;
    int bk = tid >> 6, bn = tid & 63;

    if (tid < 128) {
        int r = rt + tid;
        toks[tid] = g_slot_tok[start + ((r < ne) ? r : (ne - 1))];
    }
    __syncthreads();
    int tokA = toks[arow];

    uint32_t sA0 = (uint32_t)__cvta_generic_to_shared(&Ab[0][0]);
    uint32_t sA1 = (uint32_t)__cvta_generic_to_shared(&Ab[1][0]);
    const float* WG = wg + (size_t)e*DD*FF;
    const float* WU = wu + (size_t)e*DD*FF;

    float accg[2][4][4], accu[2][4][4];
    #pragma unroll
    for (int i = 0; i < 2; i++)
        #pragma unroll
        for (int j = 0; j < 4; j++)
            #pragma unroll
            for (int l = 0; l < 4; l++) { accg[i][j][l] = 0.f; accu[i][j][l] = 0.f; }

    uint4 av[2];
    float bg[8], bu[8];
    // tile 0 loads
    av[0] = *(const uint4*)&g_h2b[(size_t)tokA*DD + ah*16];
    av[1] = *(const uint4*)&g_h2b[(size_t)tokA*DD + ah*16 + 8];
    #pragma unroll
    for (int p = 0; p < 4; p++) {
        int kp = p*4 + bk;
        size_t off = (size_t)(2*kp)*FF + f0 + bn;
        bg[2*p]   = WG[off];       bg[2*p+1] = WG[off + FF];
        bu[2*p]   = WU[off];       bu[2*p+1] = WU[off + FF];
    }
    // store tile 0 into buf 0
    *(uint4*)&Ab[0][arow*40 + ah*16]     = av[0];
    *(uint4*)&Ab[0][arow*40 + ah*16 + 8] = av[1];
    #pragma unroll
    for (int p = 0; p < 4; p++) {
        int kp = p*4 + bk;
        Bgp[0][kp*72 + bn] = pack_bf2(bg[2*p], bg[2*p+1]);
        Bup[0][kp*72 + bn] = pack_bf2(bu[2*p], bu[2*p+1]);
    }
    __syncthreads();

    const int NT = DD/32;  // 32 tiles
    for (int it = 0; it < NT; it++) {
        int cur = it & 1;
        // prefetch next tile (regs)
        if (it + 1 < NT) {
            int k0 = (it + 1)*32;
            av[0] = *(const uint4*)&g_h2b[(size_t)tokA*DD + k0 + ah*16];
            av[1] = *(const uint4*)&g_h2b[(size_t)tokA*DD + k0 + ah*16 + 8];
            #pragma unroll
            for (int p = 0; p < 4; p++) {
                int kp = p*4 + bk;
                size_t off = (size_t)(k0 + 2*kp)*FF + f0 + bn;
                bg[2*p]   = WG[off];  bg[2*p+1] = WG[off + FF];
                bu[2*p]   = WU[off];  bu[2*p+1] = WU[off + FF];
            }
        }
        // mma on current buffer
        uint32_t sAb = cur ? sA1 : sA0;
        const uint32_t* BG = Bgp[cur];
        const uint32_t* BU = Bup[cur];
        #pragma unroll
        for (int ks = 0; ks < 2; ks++) {
            uint32_t a0[4], a1[4];
            uint32_t abyte = (uint32_t)(m_w + (lane & 15))*80u + (uint32_t)ks*32u + (lane & 16);
            ldsm4(a0, sAb + abyte);
            ldsm4(a1, sAb + abyte + 16u*80u);
            #pragma unroll
            for (int ni = 0; ni < 4; ni++) {
                int n = n_w + ni*8 + g;
                uint32_t bg0 = BG[(ks*8 + tg)*72 + n];
                uint32_t bg1 = BG[(ks*8 + tg + 4)*72 + n];
                uint32_t bu0 = BU[(ks*8 + tg)*72 + n];
                uint32_t bu1 = BU[(ks*8 + tg + 4)*72 + n];
                mma16(accg[0][ni], a0, bg0, bg1);
                mma16(accg[1][ni], a1, bg0, bg1);
                mma16(accu[0][ni], a0, bu0, bu1);
                mma16(accu[1][ni], a1, bu0, bu1);
            }
        }
        // store next tile into the other buffer
        if (it + 1 < NT) {
            int nxt = cur ^ 1;
            *(uint4*)&Ab[nxt][arow*40 + ah*16]     = av[0];
            *(uint4*)&Ab[nxt][arow*40 + ah*16 + 8] = av[1];
            #pragma unroll
            for (int p = 0; p < 4; p++) {
                int kp = p*4 + bk;
                Bgp[nxt][kp*72 + bn] = pack_bf2(bg[2*p], bg[2*p+1]);
                Bup[nxt][kp*72 + bn] = pack_bf2(bu[2*p], bu[2*p+1]);
            }
        }
        __syncthreads();
    }

    #pragma unroll
    for (int mi = 0; mi < 2; mi++)
        #pragma unroll
        for (int ni = 0; ni < 4; ni++) {
            int rb = rt + m_w + mi*16 + g;
            int c = f0 + n_w + ni*8 + 2*tg;
            #pragma unroll
            for (int hrow = 0; hrow < 2; hrow++) {
                int r = rb + hrow*8;
                if (r < ne) {
                    float gv0 = accg[mi][ni][hrow*2], gv1 = accg[mi][ni][hrow*2+1];
                    float uv0 = accu[mi][ni][hrow*2], uv1 = accu[mi][ni][hrow*2+1];
                    float ox = (gv0 / (1.f + __expf(-gv0))) * uv0;
                    float oy = (gv1 / (1.f + __expf(-gv1))) * uv1;
                    *(uint32_t*)&g_actb[(size_t)(start + r)*FF + c] = pack_bf2(ox, oy);
                }
            }
        }
}

// =====================================================================
// MoE down GEMM (bf16 m16n8k16), 128x128 tile, DOUBLE-BUFFERED pipeline
// 8 warps: 4m x 2n (warp tile 32x64). grid(DD/128, NSLOT/128, EE)
// =====================================================================
__global__ __launch_bounds__(256, 2)
void moe_down_bf16(const float* __restrict__ wd, float* __restrict__ out) {
    int e = blockIdx.z;
    int ne = g_counts[e];
    int rt = blockIdx.y*128;
    if (rt >= ne) return;
    int start = g_offsets[e];
    int n0 = blockIdx.x*128;

    __shared__ __nv_bfloat16 Ab[2][128*40];
    __shared__ uint32_t Bp[2][16*136];

    int tid = threadIdx.x;
    int lane = tid & 31, warp = tid >> 5;
    int m_w = (warp >> 1)*32, n_w = (warp & 1)*64;
    int g = lane >> 2, tg = lane & 3;
    int arow = tid >> 1, ah = tid & 1;
    int bk = tid >> 7, bn = tid & 127;

    uint32_t sA0 = (uint32_t)__cvta_generic_to_shared(&Ab[0][0]);
    uint32_t sA1 = (uint32_t)__cvta_generic_to_shared(&Ab[1][0]);
    const float* WD = wd + (size_t)e*FF*DD;

    float acc[2][8][4];
    #pragma unroll
    for (int i = 0; i < 2; i++)
        #pragma unroll
        for (int j = 0; j < 8; j++)
            #pragma unroll
            for (int l = 0; l < 4; l++) acc[i][j][l] = 0.f;

    int aslot;
    {
        int ar = start + rt + arow;
        aslot = (ar < NSLOT) ? ar : (NSLOT - 1);
    }

    uint4 av[2];
    float bv[16];
    av[0] = *(const uint4*)&g_actb[(size_t)aslot*FF + ah*16];
    av[1] = *(const uint4*)&g_actb[(size_t)aslot*FF + ah*16 + 8];
    #pragma unroll
    for (int p = 0; p < 8; p++) {
        int kp = p*2 + bk;
        size_t off = (size_t)(2*kp)*DD + n0 + bn;
        bv[2*p]   = WD[off];  bv[2*p+1] = WD[off + DD];
    }
    *(uint4*)&Ab[0][arow*40 + ah*16]     = av[0];
    *(uint4*)&Ab[0][arow*40 + ah*16 + 8] = av[1];
    #pragma unroll
    for (int p = 0; p < 8; p++) {
        int kp = p*2 + bk;
        Bp[0][kp*136 + bn] = pack_bf2(bv[2*p], bv[2*p+1]);
    }
    __syncthreads();

    const int NT = FF/32;  // 86 tiles
    for (int it = 0; it < NT; it++) {
        int cur = it & 1;
        if (it + 1 < NT) {
            int k0 = (it + 1)*32;
            av[0] = *(const uint4*)&g_actb[(size_t)aslot*FF + k0 + ah*16];
            av[1] = *(const uint4*)&g_actb[(size_t)aslot*FF + k0 + ah*16 + 8];
            #pragma unroll
            for (int p = 0; p < 8; p++) {
                int kp = p*2 + bk;
                size_t off = (size_t)(k0 + 2*kp)*DD + n0 + bn;
                bv[2*p]   = WD[off];  bv[2*p+1] = WD[off + DD];
            }
        }
        uint32_t sAb = cur ? sA1 : sA0;
        const uint32_t* BB = Bp[cur];
        #pragma unroll
        for (int ks = 0; ks < 2; ks++) {
            uint32_t a0[4], a1[4];
            uint32_t abyte = (uint32_t)(m_w + (lane & 15))*80u + (uint32_t)ks*32u + (lane & 16);
            ldsm4(a0, sAb + abyte);
            ldsm4(a1, sAb + abyte + 16u*80u);
            #pragma unroll
            for (int ni = 0; ni < 8; ni++) {
                int n = n_w + ni*8 + g;
                uint32_t b0 = BB[(ks*8 + tg)*136 + n];
                uint32_t b1 = BB[(ks*8 + tg + 4)*136 + n];
                mma16(acc[0][ni], a0, b0, b1);
                mma16(acc[1][ni], a1, b0, b1);
            }
        }
        if (it + 1 < NT) {
            int nxt = cur ^ 1;
            *(uint4*)&Ab[nxt][arow*40 + ah*16]     = av[0];
            *(uint4*)&Ab[nxt][arow*40 + ah*16 + 8] = av[1];
            #pragma unroll
            for (int p = 0; p < 8; p++) {
                int kp = p*2 + bk;
                Bp[nxt][kp*136 + bn] = pack_bf2(bv[2*p], bv[2*p+1]);
            }
        }
        __syncthreads();
    }

    #pragma unroll
    for (int mi = 0; mi < 2; mi++)
        #pragma unroll
        for (int ni = 0; ni < 8; ni++) {
            int rb = rt + m_w + mi*16 + g;
            int c = n0 + n_w + ni*8 + 2*tg;
            #pragma unroll
            for (int hrow = 0; hrow < 2; hrow++) {
                int r = rb + hrow*8;
                if (r < ne) {
                    int tok = g_slot_tok[start + r];
                    float w = g_slot_w[start + r];
                    atomicAdd(&out[(size_t)tok*DD + c],     w*acc[mi][ni][hrow*2]);
                    atomicAdd(&out[(size_t)tok*DD + c + 1], w*acc[mi][ni][hrow*2+1]);
                }
            }
        }
}

// ---------------- aux loss ----------------
__global__ void aux_kernel(float* __restrict__ out, int out_size) {
    if (threadIdx.x == 0 && out_size > TT*DD) {
        float aux = 0.f;
        for (int e = 0; e < EE; e++) {
            float frac = (float)g_counts[e] / (float)(TT*TOPK);
            float load = g_load[e] / (float)TT;
            aux += frac*load;
        }
        out[TT*DD] = LB * (float)EE * aux;
    }
}

// ---------------- launch ----------------
extern "C" void kernel_launch(void* const* d_in, const int* in_sizes, int n_in,
                              void* d_out, int out_size) {
    const float* x       = (const float*)d_in[0];
    const float* g1      = (const float*)d_in[1];
    const float* g2      = (const float*)d_in[2];
    const float* wq      = (const float*)d_in[3];
    const float* wk      = (const float*)d_in[4];
    const float* wv      = (const float*)d_in[5];
    const float* wo      = (const float*)d_in[6];
    const float* gate_w  = (const float*)d_in[7];
    const float* we_gate = (const float*)d_in[8];
    const float* we_up   = (const float*)d_in[9];
    const float* we_down = (const float*)d_in[10];
    float* out = (float*)d_out;

    static float *p_h = nullptr, *p_attn = nullptr;
    if (!p_h) {
        cudaGetSymbolAddress((void**)&p_h, g_h);
        cudaGetSymbolAddress((void**)&p_attn, g_attn);
        cudaFuncSetAttribute(attn_tf32_kernel, cudaFuncAttributeMaxDynamicSharedMemorySize,
                             ATTN_SMEM);
    }

    clear_kernel<<<1, 32>>>();
    rmsnorm_kernel<<<TT, 256>>>(x, g1, p_h);
    qkv_tf32_kernel<<<dim3(24, TT/128), 256>>>(wq, wk, wv);
    rope_kernel<<<512, 256>>>();
    attn_tf32_kernel<<<dim3(2*TT/64, HQ), 128, ATTN_SMEM>>>();
    attn_combine_kernel<<<TT, 256>>>();
    gemm_tf32_kernel<<<dim3(DD/64, TT/128), 256>>>(p_attn, wo, out, TT, DD, DD, x);
    rmsnorm_gate_kernel<<<TT, 256>>>(out, g2, gate_w);
    route_kernel<<<1, 1024>>>();
    moe_act_bf16<<<dim3(FF/64, NSLOT/128, EE), 256>>>(we_gate, we_up);
    moe_down_bf16<<<dim3(DD/128, NSLOT/128, EE), 256>>>(we_down, out);
    aux_kernel<<<1, 32>>>(out, out_size);
}

// round 17
// speedup vs baseline: 1.5368x; 1.0095x over previous
#include <cuda_runtime.h>
#include <cuda_bf16.h>
#include <math.h>
#include <stdint.h>

// Problem constants
#define TT 2048
#define DD 1024
#define HQ 16
#define HKV 4
#define HD 64
#define EE 8
#define TOPK 2
#define FF 2752
#define NSLOT (TT*TOPK)
#define SCALE 0.125f
#define LB 0.01f

// ---------------- device scratch (no allocs allowed) ----------------
__device__ float g_h[TT*DD];
__device__ float g_q[TT*HQ*HD];
__device__ float g_k[TT*HKV*HD];
__device__ float g_v[TT*HKV*HD];
__device__ float g_attn[TT*HQ*HD];
__device__ __nv_bfloat16 g_h2b[TT*DD];
__device__ int   g_sel[TT*TOPK];
__device__ float g_selw[TT*TOPK];
__device__ int   g_counts[EE];
__device__ int   g_offsets[EE+1];
__device__ int   g_cursor[EE];
__device__ float g_load[EE];
__device__ int   g_slot_tok[NSLOT];
__device__ float g_slot_w[NSLOT];
__device__ __nv_bfloat16 g_actb[(size_t)NSLOT*FF];  // 22.5 MB
// split-KV attention partials
__device__ float g_po0[TT*DD];
__device__ float g_po1[TT*DD];
__device__ float g_pm[2][TT*HQ];
__device__ float g_pl[2][TT*HQ];

// ---------------- helpers ----------------
__device__ __forceinline__ float tf32r(float x) {
    float y;
    asm("cvt.rna.tf32.f32 %0, %1;" : "=f"(y) : "f"(x));
    return y;
}

__device__ __forceinline__ void ldsm4(uint32_t a[4], uint32_t addr) {
    asm volatile("ldmatrix.sync.aligned.m8n8.x4.shared.b16 {%0,%1,%2,%3}, [%4];"
                 : "=r"(a[0]), "=r"(a[1]), "=r"(a[2]), "=r"(a[3]) : "r"(addr));
}

__device__ __forceinline__ void mma8(float d[4], const uint32_t a[4],
                                     uint32_t b0, uint32_t b1) {
    asm volatile(
        "mma.sync.aligned.m16n8k8.row.col.f32.tf32.tf32.f32 "
        "{%0,%1,%2,%3}, {%4,%5,%6,%7}, {%8,%9}, {%0,%1,%2,%3};"
        : "+f"(d[0]), "+f"(d[1]), "+f"(d[2]), "+f"(d[3])
        : "r"(a[0]), "r"(a[1]), "r"(a[2]), "r"(a[3]), "r"(b0), "r"(b1));
}

__device__ __forceinline__ void mma16(float d[4], const uint32_t a[4],
                                      uint32_t b0, uint32_t b1) {
    asm volatile(
        "mma.sync.aligned.m16n8k16.row.col.f32.bf16.bf16.f32 "
        "{%0,%1,%2,%3}, {%4,%5,%6,%7}, {%8,%9}, {%0,%1,%2,%3};"
        : "+f"(d[0]), "+f"(d[1]), "+f"(d[2]), "+f"(d[3])
        : "r"(a[0]), "r"(a[1]), "r"(a[2]), "r"(a[3]), "r"(b0), "r"(b1));
}

__device__ __forceinline__ uint32_t pack_bf2(float lo, float hi) {
    __nv_bfloat16 a = __float2bfloat16(lo), b = __float2bfloat16(hi);
    uint16_t ua = *(uint16_t*)&a, ub = *(uint16_t*)&b;
    return (uint32_t)ua | ((uint32_t)ub << 16);
}

// ---------------- rmsnorm (rmsnorm1 only) ----------------
__global__ void rmsnorm_kernel(const float* __restrict__ x, const float* __restrict__ g,
                               float* __restrict__ out) {
    int t = blockIdx.x;
    const float* xr = x + (size_t)t*DD;
    __shared__ float red[256];
    int tid = threadIdx.x;
    float s = 0.f;
    for (int d = tid; d < DD; d += 256) { float v = xr[d]; s += v*v; }
    red[tid] = s; __syncthreads();
    for (int st = 128; st > 0; st >>= 1) {
        if (tid < st) red[tid] += red[tid+st];
        __syncthreads();
    }
    float inv = rsqrtf(red[0]/(float)DD + 1e-6f);
    float* o = out + (size_t)t*DD;
    for (int d = tid; d < DD; d += 256) o[d] = xr[d]*g[d]*inv;
}

// =====================================================================
// tf32 GEMM (128x64 tile, 8 warps), 2 blocks/SM — float2 B fill
// =====================================================================
__global__ __launch_bounds__(256, 2)
void gemm_tf32_kernel(const float* __restrict__ A, const float* __restrict__ B,
                      float* __restrict__ C, int M, int N, int K,
                      const float* __restrict__ res) {
    __shared__ float As_[128][36];
    __shared__ float Bs_[32][72];
    int m0 = blockIdx.y*128, n0 = blockIdx.x*64;
    int tid = threadIdx.x;
    int lane = tid & 31, warp = tid >> 5;
    int m_w = (warp >> 1)*32, n_w = (warp & 1)*32;
    int g = lane >> 2, tg = lane & 3;
    int rr = tid >> 3, cc = tid & 7;

    uint32_t sA = (uint32_t)__cvta_generic_to_shared(&As_[0][0]);

    float acc[2][4][4];
    #pragma unroll
    for (int i = 0; i < 2; i++)
        #pragma unroll
        for (int j = 0; j < 4; j++)
            #pragma unroll
            for (int l = 0; l < 4; l++) acc[i][j][l] = 0.f;

    float4 av[4];
    float2 bv[4];
    #pragma unroll
    for (int p = 0; p < 4; p++)
        av[p] = *(const float4*)&A[(size_t)(m0 + rr + p*32)*K + cc*4];
    #pragma unroll
    for (int p = 0; p < 4; p++) {
        int id = tid + p*256;
        bv[p] = *(const float2*)&B[(size_t)(id >> 5)*N + n0 + (id & 31)*2];
    }

    for (int k0 = 0; k0 < K; k0 += 32) {
        __syncthreads();
        #pragma unroll
        for (int p = 0; p < 4; p++) {
            float4 v = av[p];
            v.x = tf32r(v.x); v.y = tf32r(v.y); v.z = tf32r(v.z); v.w = tf32r(v.w);
            *(float4*)&As_[rr + p*32][cc*4] = v;
        }
        #pragma unroll
        for (int p = 0; p < 4; p++) {
            int id = tid + p*256;
            *(float2*)&Bs_[id >> 5][(id & 31)*2] =
                make_float2(tf32r(bv[p].x), tf32r(bv[p].y));
        }
        __syncthreads();
        if (k0 + 32 < K) {
            #pragma unroll
            for (int p = 0; p < 4; p++)
                av[p] = *(const float4*)&A[(size_t)(m0 + rr + p*32)*K + k0 + 32 + cc*4];
            #pragma unroll
            for (int p = 0; p < 4; p++) {
                int id = tid + p*256;
                bv[p] = *(const float2*)&B[(size_t)(k0 + 32 + (id >> 5))*N + n0 + (id & 31)*2];
            }
        }
        #pragma unroll
        for (int ks = 0; ks < 4; ks++) {
            uint32_t a0[4], a1[4];
            int acol = ks*8 + ((lane & 16) >> 2);
            int arow = m_w + (lane & 15);
            ldsm4(a0, sA + (uint32_t)(arow*36 + acol)*4u);
            ldsm4(a1, sA + (uint32_t)((arow + 16)*36 + acol)*4u);
            #pragma unroll
            for (int ni = 0; ni < 4; ni++) {
                uint32_t b0 = __float_as_uint(Bs_[ks*8 + tg][n_w + ni*8 + g]);
                uint32_t b1 = __float_as_uint(Bs_[ks*8 + tg + 4][n_w + ni*8 + g]);
                mma8(acc[0][ni], a0, b0, b1);
                mma8(acc[1][ni], a1, b0, b1);
            }
        }
    }

    #pragma unroll
    for (int mi = 0; mi < 2; mi++)
        #pragma unroll
        for (int ni = 0; ni < 4; ni++) {
            int rbase = m0 + m_w + mi*16 + g;
            int c = n0 + n_w + ni*8 + 2*tg;
            #pragma unroll
            for (int hrow = 0; hrow < 2; hrow++) {
                int r = rbase + hrow*8;
                float2 v = make_float2(acc[mi][ni][hrow*2], acc[mi][ni][hrow*2+1]);
                if (res) {
                    float2 rv = *(const float2*)&res[(size_t)r*N + c];
                    v.x += rv.x; v.y += rv.y;
                }
                *(float2*)&C[(size_t)r*N + c] = v;
            }
        }
}

// =====================================================================
// fused QKV projection — float2 B fill
// =====================================================================
__global__ __launch_bounds__(256, 2)
void qkv_tf32_kernel(const float* __restrict__ wq, const float* __restrict__ wk,
                     const float* __restrict__ wv) {
    __shared__ float As_[128][36];
    __shared__ float Bs_[32][72];
    int n0g = blockIdx.x*64;
    const float* B; float* C; int N; int n0;
    if (n0g < 1024)      { B = wq; C = g_q; N = HQ*HD;  n0 = n0g; }
    else if (n0g < 1280) { B = wk; C = g_k; N = HKV*HD; n0 = n0g - 1024; }
    else                 { B = wv; C = g_v; N = HKV*HD; n0 = n0g - 1280; }
    const float* A = g_h;
    int m0 = blockIdx.y*128;
    int tid = threadIdx.x;
    int lane = tid & 31, warp = tid >> 5;
    int m_w = (warp >> 1)*32, n_w = (warp & 1)*32;
    int g = lane >> 2, tg = lane & 3;
    int rr = tid >> 3, cc = tid & 7;

    uint32_t sA = (uint32_t)__cvta_generic_to_shared(&As_[0][0]);

    float acc[2][4][4];
    #pragma unroll
    for (int i = 0; i < 2; i++)
        #pragma unroll
        for (int j = 0; j < 4; j++)
            #pragma unroll
            for (int l = 0; l < 4; l++) acc[i][j][l] = 0.f;

    float4 av[4];
    float2 bv[4];
    #pragma unroll
    for (int p = 0; p < 4; p++)
        av[p] = *(const float4*)&A[(size_t)(m0 + rr + p*32)*DD + cc*4];
    #pragma unroll
    for (int p = 0; p < 4; p++) {
        int id = tid + p*256;
        bv[p] = *(const float2*)&B[(size_t)(id >> 5)*N + n0 + (id & 31)*2];
    }

    for (int k0 = 0; k0 < DD; k0 += 32) {
        __syncthreads();
        #pragma unroll
        for (int p = 0; p < 4; p++) {
            float4 v = av[p];
            v.x = tf32r(v.x); v.y = tf32r(v.y); v.z = tf32r(v.z); v.w = tf32r(v.w);
            *(float4*)&As_[rr + p*32][cc*4] = v;
        }
        #pragma unroll
        for (int p = 0; p < 4; p++) {
            int id = tid + p*256;
            *(float2*)&Bs_[id >> 5][(id & 31)*2] =
                make_float2(tf32r(bv[p].x), tf32r(bv[p].y));
        }
        __syncthreads();
        if (k0 + 32 < DD) {
            #pragma unroll
            for (int p = 0; p < 4; p++)
                av[p] = *(const float4*)&A[(size_t)(m0 + rr + p*32)*DD + k0 + 32 + cc*4];
            #pragma unroll
            for (int p = 0; p < 4; p++) {
                int id = tid + p*256;
                bv[p] = *(const float2*)&B[(size_t)(k0 + 32 + (id >> 5))*N + n0 + (id & 31)*2];
            }
        }
        #pragma unroll
        for (int ks = 0; ks < 4; ks++) {
            uint32_t a0[4], a1[4];
            int acol = ks*8 + ((lane & 16) >> 2);
            int arow = m_w + (lane & 15);
            ldsm4(a0, sA + (uint32_t)(arow*36 + acol)*4u);
            ldsm4(a1, sA + (uint32_t)((arow + 16)*36 + acol)*4u);
            #pragma unroll
            for (int ni = 0; ni < 4; ni++) {
                uint32_t b0 = __float_as_uint(Bs_[ks*8 + tg][n_w + ni*8 + g]);
                uint32_t b1 = __float_as_uint(Bs_[ks*8 + tg + 4][n_w + ni*8 + g]);
                mma8(acc[0][ni], a0, b0, b1);
                mma8(acc[1][ni], a1, b0, b1);
            }
        }
    }

    #pragma unroll
    for (int mi = 0; mi < 2; mi++)
        #pragma unroll
        for (int ni = 0; ni < 4; ni++) {
            int rbase = m0 + m_w + mi*16 + g;
            int c = n0 + n_w + ni*8 + 2*tg;
            #pragma unroll
            for (int hrow = 0; hrow < 2; hrow++) {
                int r = rbase + hrow*8;
                *(float2*)&C[(size_t)r*N + c] =
                    make_float2(acc[mi][ni][hrow*2], acc[mi][ni][hrow*2+1]);
            }
        }
}

// ---------------- RoPE (grid-stride, exp2f freq) ----------------
__global__ void rope_kernel() {
    const int total = TT*(HQ+HKV)*32;
    const float LOG2_10000_32 = 0.4152410118609203f;
    for (int i = blockIdx.x*blockDim.x + threadIdx.x; i < total;
         i += gridDim.x*blockDim.x) {
        int d = i & 31;
        int tmp = i >> 5;
        int hh = tmp % (HQ+HKV);
        int t = tmp / (HQ+HKV);
        float* p;
        if (hh < HQ) p = g_q + (size_t)t*HQ*HD + hh*HD;
        else         p = g_k + (size_t)t*HKV*HD + (hh-HQ)*HD;
        float inv = exp2f(-(float)d * LOG2_10000_32);
        float ang = (float)t * inv;
        float c = cosf(ang), s = sinf(ang);
        float x1 = p[d], x2 = p[d+32];
        p[d]    = x1*c - x2*s;
        p[d+32] = x2*c + x1*s;
    }
}

// =====================================================================
// flash attention tf32, SPLIT-KV
// =====================================================================
#define ATTN_SMEM ((2*64*68 + 64*72)*4)
__global__ __launch_bounds__(128, 3)
void attn_tf32_kernel() {
    extern __shared__ float sm[];
    float* Qs = sm;
    float* KP = sm + 64*68;
    float* Vs = sm + 2*64*68;
    int bx = (int)blockIdx.x >> 1;
    int piece = (int)blockIdx.x & 1;
    int qt = (int)(gridDim.x >> 1) - 1 - bx;
    int mid = (qt + 1) >> 1;
    int kt_lo = piece ? mid : 0;
    int kt_hi = piece ? (qt + 1) : mid;
    int head = blockIdx.y;
    int kvh = head >> 2;
    int qs0 = qt*64;
    int tid = threadIdx.x;
    int lane = tid & 31, warp = tid >> 5;
    int r0 = warp*16;
    int g = lane >> 2, tg = lane & 3;
    uint32_t sQ = (uint32_t)__cvta_generic_to_shared(Qs);
    uint32_t sKP = (uint32_t)__cvta_generic_to_shared(KP);

    #pragma unroll
    for (int it = 0; it < 8; it++) {
        int idx = it*128 + tid;
        int r = idx >> 4, c4 = (idx & 15)*4;
        float4 v = *(const float4*)&g_q[(size_t)(qs0+r)*DD + head*HD + c4];
        v.x = tf32r(v.x); v.y = tf32r(v.y); v.z = tf32r(v.z); v.w = tf32r(v.w);
        *(float4*)&Qs[r*68 + c4] = v;
    }

    float o[8][4];
    #pragma unroll
    for (int ni = 0; ni < 8; ni++)
        #pragma unroll
        for (int j = 0; j < 4; j++) o[ni][j] = 0.f;
    float m0 = -1e30f, m1 = -1e30f, l0 = 0.f, l1 = 0.f;
    int qr0 = qs0 + r0 + g, qr1 = qr0 + 8;

    for (int kt = kt_lo; kt < kt_hi; kt++) {
        __syncthreads();
        #pragma unroll
        for (int it = 0; it < 8; it++) {
            int idx = it*128 + tid;
            int r = idx >> 4, c4 = (idx & 15)*4;
            size_t goff = (size_t)(kt*64+r)*(HKV*HD) + kvh*HD + c4;
            float4 kv = *(const float4*)&g_k[goff];
            kv.x = tf32r(kv.x); kv.y = tf32r(kv.y); kv.z = tf32r(kv.z); kv.w = tf32r(kv.w);
            *(float4*)&KP[r*68 + c4] = kv;
            float4 vv = *(const float4*)&g_v[goff];
            vv.x = tf32r(vv.x); vv.y = tf32r(vv.y); vv.z = tf32r(vv.z); vv.w = tf32r(vv.w);
            *(float4*)&Vs[r*72 + c4] = vv;
        }
        __syncthreads();

        float s[8][4];
        #pragma unroll
        for (int ni = 0; ni < 8; ni++)
            #pragma unroll
            for (int j = 0; j < 4; j++) s[ni][j] = 0.f;
        #pragma unroll
        for (int kc = 0; kc < 8; kc++) {
            uint32_t a[4];
            ldsm4(a, sQ + (uint32_t)((r0 + (lane & 15))*68 + kc*8 + ((lane & 16) >> 2))*4u);
            #pragma unroll
            for (int ni = 0; ni < 8; ni++) {
                uint32_t b0 = __float_as_uint(KP[(ni*8+g)*68 + kc*8 + tg]);
                uint32_t b1 = __float_as_uint(KP[(ni*8+g)*68 + kc*8 + tg + 4]);
                mma8(s[ni], a, b0, b1);
            }
        }
        __syncthreads();

        float tmax0 = -1e30f, tmax1 = -1e30f;
        #pragma unroll
        for (int ni = 0; ni < 8; ni++) {
            #pragma unroll
            for (int j = 0; j < 2; j++) {
                int c = kt*64 + ni*8 + 2*tg + j;
                float v0 = s[ni][j]*SCALE;
                float v1 = s[ni][j+2]*SCALE;
                if (c > qr0) v0 = -1e30f;
                if (c > qr1) v1 = -1e30f;
                s[ni][j] = v0; s[ni][j+2] = v1;
                tmax0 = fmaxf(tmax0, v0); tmax1 = fmaxf(tmax1, v1);
            }
        }
        tmax0 = fmaxf(tmax0, __shfl_xor_sync(0xffffffffu, tmax0, 1));
        tmax0 = fmaxf(tmax0, __shfl_xor_sync(0xffffffffu, tmax0, 2));
        tmax1 = fmaxf(tmax1, __shfl_xor_sync(0xffffffffu, tmax1, 1));
        tmax1 = fmaxf(tmax1, __shfl_xor_sync(0xffffffffu, tmax1, 2));
        float mn0 = fmaxf(m0, tmax0), mn1 = fmaxf(m1, tmax1);
        float a0 = __expf(m0 - mn0), a1 = __expf(m1 - mn1);
        m0 = mn0; m1 = mn1;

        float ls0 = 0.f, ls1 = 0.f;
        #pragma unroll
        for (int ni = 0; ni < 8; ni++) {
            float p0 = __expf(s[ni][0] - m0), p1 = __expf(s[ni][1] - m0);
            float p2 = __expf(s[ni][2] - m1), p3 = __expf(s[ni][3] - m1);
            ls0 += p0 + p1; ls1 += p2 + p3;
            *(float2*)&KP[(r0+g)*68 + ni*8 + 2*tg]   = make_float2(tf32r(p0), tf32r(p1));
            *(float2*)&KP[(r0+g+8)*68 + ni*8 + 2*tg] = make_float2(tf32r(p2), tf32r(p3));
        }
        ls0 += __shfl_xor_sync(0xffffffffu, ls0, 1);
        ls0 += __shfl_xor_sync(0xffffffffu, ls0, 2);
        ls1 += __shfl_xor_sync(0xffffffffu, ls1, 1);
        ls1 += __shfl_xor_sync(0xffffffffu, ls1, 2);
        l0 = l0*a0 + ls0; l1 = l1*a1 + ls1;
        #pragma unroll
        for (int ni = 0; ni < 8; ni++) {
            o[ni][0] *= a0; o[ni][1] *= a0;
            o[ni][2] *= a1; o[ni][3] *= a1;
        }
        __syncwarp();

        #pragma unroll
        for (int kc = 0; kc < 8; kc++) {
            uint32_t a[4];
            ldsm4(a, sKP + (uint32_t)((r0 + (lane & 15))*68 + kc*8 + ((lane & 16) >> 2))*4u);
            #pragma unroll
            for (int ni = 0; ni < 8; ni++) {
                uint32_t b0 = __float_as_uint(Vs[(kc*8+tg)*72 + ni*8 + g]);
                uint32_t b1 = __float_as_uint(Vs[(kc*8+tg+4)*72 + ni*8 + g]);
                mma8(o[ni], a, b0, b1);
            }
        }
    }

    float* PO = piece ? g_po1 : g_po0;
    #pragma unroll
    for (int ni = 0; ni < 8; ni++) {
        *(float2*)&PO[(size_t)qr0*DD + head*HD + ni*8 + 2*tg] =
            make_float2(o[ni][0], o[ni][1]);
        *(float2*)&PO[(size_t)qr1*DD + head*HD + ni*8 + 2*tg] =
            make_float2(o[ni][2], o[ni][3]);
    }
    if (tg == 0) {
        g_pm[piece][qr0*HQ + head] = m0;
        g_pl[piece][qr0*HQ + head] = l0;
        g_pm[piece][qr1*HQ + head] = m1;
        g_pl[piece][qr1*HQ + head] = l1;
    }
}

// ---------------- combine split-KV partials ----------------
__global__ void attn_combine_kernel() {
    int t = blockIdx.x;
    int tid = threadIdx.x;
    #pragma unroll
    for (int i = 0; i < 4; i++) {
        int idx = tid + i*256;
        int head = idx >> 6, d = idx & 63;
        float m0 = g_pm[0][t*HQ + head], m1 = g_pm[1][t*HQ + head];
        float l0 = g_pl[0][t*HQ + head], l1 = g_pl[1][t*HQ + head];
        float m = fmaxf(m0, m1);
        float c0 = __expf(m0 - m), c1 = __expf(m1 - m);
        float l = l0*c0 + l1*c1;
        size_t off = (size_t)t*DD + head*HD + d;
        g_attn[off] = (g_po0[off]*c0 + g_po1[off]*c1) / l;
    }
}

// ---------------- clear counters ----------------
__global__ void clear_kernel() {
    int i = threadIdx.x;
    if (i < EE) { g_counts[i] = 0; g_cursor[i] = 0; g_load[i] = 0.f; }
}

// ---------------- fused rmsnorm2 + gating ----------------
__global__ void rmsnorm_gate_kernel(const float* __restrict__ x, const float* __restrict__ g,
                                    const float* __restrict__ gate_w) {
    int t = blockIdx.x;
    int tid = threadIdx.x;
    int lane = tid & 31, warp = tid >> 5;
    const float* xr = x + (size_t)t*DD;
    __shared__ float red[256];
    float s = 0.f;
    for (int d = tid; d < DD; d += 256) { float v = xr[d]; s += v*v; }
    red[tid] = s; __syncthreads();
    for (int st = 128; st > 0; st >>= 1) {
        if (tid < st) red[tid] += red[tid+st];
        __syncthreads();
    }
    float inv = rsqrtf(red[0]/(float)DD + 1e-6f);

    float acc[EE];
    #pragma unroll
    for (int e = 0; e < EE; e++) acc[e] = 0.f;
    for (int d = tid; d < DD; d += 256) {
        float v = xr[d]*g[d]*inv;
        g_h2b[(size_t)t*DD + d] = __float2bfloat16(v);
        #pragma unroll
        for (int e = 0; e < EE; e++) acc[e] += v*gate_w[d*EE + e];
    }
    #pragma unroll
    for (int e = 0; e < EE; e++) {
        #pragma unroll
        for (int st = 16; st > 0; st >>= 1)
            acc[e] += __shfl_xor_sync(0xffffffffu, acc[e], st);
    }
    __shared__ float part[8][EE];
    if (lane == 0) {
        #pragma unroll
        for (int e = 0; e < EE; e++) part[warp][e] = acc[e];
    }
    __syncthreads();
    if (tid == 0) {
        float p[EE];
        #pragma unroll
        for (int e = 0; e < EE; e++) {
            float v = 0.f;
            #pragma unroll
            for (int w = 0; w < 8; w++) v += part[w][e];
            p[e] = v;
        }
        float mx = p[0];
        for (int e = 1; e < EE; e++) mx = fmaxf(mx, p[e]);
        float ssum = 0.f;
        for (int e = 0; e < EE; e++) { p[e] = __expf(p[e]-mx); ssum += p[e]; }
        for (int e = 0; e < EE; e++) p[e] /= ssum;
        int i0 = 0;
        for (int e = 1; e < EE; e++) if (p[e] > p[i0]) i0 = e;
        int i1 = (i0 == 0) ? 1 : 0;
        for (int e = 0; e < EE; e++) if (e != i0 && p[e] > p[i1]) i1 = e;
        float v0 = p[i0], v1 = p[i1];
        float s2 = v0 + v1 + 1e-8f;
        g_sel[t*2] = i0;   g_selw[t*2] = v0/s2;
        g_sel[t*2+1] = i1; g_selw[t*2+1] = v1/s2;
        atomicAdd(&g_counts[i0], 1);
        atomicAdd(&g_counts[i1], 1);
        for (int e = 0; e < EE; e++) atomicAdd(&g_load[e], p[e]);
    }
}

// ---------------- fused offsets + scatter (single block) ----------------
__global__ void route_kernel() {
    if (threadIdx.x == 0) {
        int off = 0;
        for (int e = 0; e < EE; e++) { g_offsets[e] = off; off += g_counts[e]; }
        g_offsets[EE] = off;
    }
    __syncthreads();
    for (int n = threadIdx.x; n < TT; n += blockDim.x) {
        #pragma unroll
        for (int j = 0; j < TOPK; j++) {
            int e = g_sel[n*2+j];
            int pos = g_offsets[e] + atomicAdd(&g_cursor[e], 1);
            g_slot_tok[pos] = n;
            g_slot_w[pos] = g_selw[n*2+j];
        }
    }
}

// =====================================================================
// MoE gate+up GEMM (bf16 m16n8k16), 128-row M tile, double-buffered,
// float2-vectorized B fill. 8 warps: 4m x 2n. grid(FF/64, NSLOT/128, EE)
// =====================================================================
__global__ __launch_bounds__(256, 2)
void moe_act_bf16(const float* __restrict__ wg, const float* __restrict__ wu) {
    int e = blockIdx.z;
    int ne = g_counts[e];
    int rt = blockIdx.y*128;
    if (rt >= ne) return;
    int start = g_offsets[e];
    int f0 = blockIdx.x*64;

    __shared__ int toks[128];
    __shared__ __nv_bfloat16 Ab[2][128*40];
    __shared__ uint32_t Bgp[2][16*72];
    __shared__ uint32_t Bup[2][16*72];

    int tid = threadIdx.x;
    int lane = tid & 31, warp = tid >> 5;
    int m_w = (warp >> 1)*32, n_w = (warp & 1)*32;
    int g = lane >> 2, tg = lane & 3;
    int arow = tid >> 1, ah = tid & 1;

    if (tid < 128) {
        int r = rt + tid;
        toks[tid] = g_slot_tok[start + ((r < ne) ? r : (ne - 1))];
    }
    __syncthreads();
    int tokA = toks[arow];

    uint32_t sA0 = (uint32_t)__cvta_generic_to_shared(&Ab[0][0]);
    uint32_t sA1 = (uint32_t)__cvta_generic_to_shared(&Ab[1][0]);
    const float* WG = wg + (size_t)e*DD*FF;
    const float* WU = wu + (size_t)e*DD*FF;

    float accg[2][4][4], accu[2][4][4];
    #pragma unroll
    for (int i = 0; i < 2; i++)
        #pragma unroll
        for (int j = 0; j < 4; j++)
            #pragma unroll
            for (int l = 0; l < 4; l++) { accg[i][j][l] = 0.f; accu[i][j][l] = 0.f; }

    uint4 av[2];
    float2 pg[2][2], pu[2][2];   // [item][row]
    // tile 0 loads
    av[0] = *(const uint4*)&g_h2b[(size_t)tokA*DD + ah*16];
    av[1] = *(const uint4*)&g_h2b[(size_t)tokA*DD + ah*16 + 8];
    #pragma unroll
    for (int it2 = 0; it2 < 2; it2++) {
        int id = tid + it2*256;
        int kp = id >> 5, n = (id & 31)*2;
        size_t off = (size_t)(2*kp)*FF + f0 + n;
        pg[it2][0] = *(const float2*)&WG[off];
        pg[it2][1] = *(const float2*)&WG[off + FF];
        pu[it2][0] = *(const float2*)&WU[off];
        pu[it2][1] = *(const float2*)&WU[off + FF];
    }
    // store tile 0 into buf 0
    *(uint4*)&Ab[0][arow*40 + ah*16]     = av[0];
    *(uint4*)&Ab[0][arow*40 + ah*16 + 8] = av[1];
    #pragma unroll
    for (int it2 = 0; it2 < 2; it2++) {
        int id = tid + it2*256;
        int kp = id >> 5, n = (id & 31)*2;
        uint2 vg = make_uint2(pack_bf2(pg[it2][0].x, pg[it2][1].x),
                              pack_bf2(pg[it2][0].y, pg[it2][1].y));
        uint2 vu = make_uint2(pack_bf2(pu[it2][0].x, pu[it2][1].x),
                              pack_bf2(pu[it2][0].y, pu[it2][1].y));
        *(uint2*)&Bgp[0][kp*72 + n] = vg;
        *(uint2*)&Bup[0][kp*72 + n] = vu;
    }
    __syncthreads();

    const int NT = DD/32;
    for (int it = 0; it < NT; it++) {
        int cur = it & 1;
        if (it + 1 < NT) {
            int k0 = (it + 1)*32;
            av[0] = *(const uint4*)&g_h2b[(size_t)tokA*DD + k0 + ah*16];
            av[1] = *(const uint4*)&g_h2b[(size_t)tokA*DD + k0 + ah*16 + 8];
            #pragma unroll
            for (int it2 = 0; it2 < 2; it2++) {
                int id = tid + it2*256;
                int kp = id >> 5, n = (id & 31)*2;
                size_t off = (size_t)(k0 + 2*kp)*FF + f0 + n;
                pg[it2][0] = *(const float2*)&WG[off];
                pg[it2][1] = *(const float2*)&WG[off + FF];
                pu[it2][0] = *(const float2*)&WU[off];
                pu[it2][1] = *(const float2*)&WU[off + FF];
            }
        }
        uint32_t sAb = cur ? sA1 : sA0;
        const uint32_t* BG = Bgp[cur];
        const uint32_t* BU = Bup[cur];
        #pragma unroll
        for (int ks = 0; ks < 2; ks++) {
            uint32_t a0[4], a1[4];
            uint32_t abyte = (uint32_t)(m_w + (lane & 15))*80u + (uint32_t)ks*32u + (lane & 16);
            ldsm4(a0, sAb + abyte);
            ldsm4(a1, sAb + abyte + 16u*80u);
            #pragma unroll
            for (int ni = 0; ni < 4; ni++) {
                int n = n_w + ni*8 + g;
                uint32_t bg0 = BG[(ks*8 + tg)*72 + n];
                uint32_t bg1 = BG[(ks*8 + tg + 4)*72 + n];
                uint32_t bu0 = BU[(ks*8 + tg)*72 + n];
                uint32_t bu1 = BU[(ks*8 + tg + 4)*72 + n];
                mma16(accg[0][ni], a0, bg0, bg1);
                mma16(accg[1][ni], a1, bg0, bg1);
                mma16(accu[0][ni], a0, bu0, bu1);
                mma16(accu[1][ni], a1, bu0, bu1);
            }
        }
        if (it + 1 < NT) {
            int nxt = cur ^ 1;
            *(uint4*)&Ab[nxt][arow*40 + ah*16]     = av[0];
            *(uint4*)&Ab[nxt][arow*40 + ah*16 + 8] = av[1];
            #pragma unroll
            for (int it2 = 0; it2 < 2; it2++) {
                int id = tid + it2*256;
                int kp = id >> 5, n = (id & 31)*2;
                uint2 vg = make_uint2(pack_bf2(pg[it2][0].x, pg[it2][1].x),
                                      pack_bf2(pg[it2][0].y, pg[it2][1].y));
                uint2 vu = make_uint2(pack_bf2(pu[it2][0].x, pu[it2][1].x),
                                      pack_bf2(pu[it2][0].y, pu[it2][1].y));
                *(uint2*)&Bgp[nxt][kp*72 + n] = vg;
                *(uint2*)&Bup[nxt][kp*72 + n] = vu;
            }
        }
        __syncthreads();
    }

    #pragma unroll
    for (int mi = 0; mi < 2; mi++)
        #pragma unroll
        for (int ni = 0; ni < 4; ni++) {
            int rb = rt + m_w + mi*16 + g;
            int c = f0 + n_w + ni*8 + 2*tg;
            #pragma unroll
            for (int hrow = 0; hrow < 2; hrow++) {
                int r = rb + hrow*8;
                if (r < ne) {
                    float gv0 = accg[mi][ni][hrow*2], gv1 = accg[mi][ni][hrow*2+1];
                    float uv0 = accu[mi][ni][hrow*2], uv1 = accu[mi][ni][hrow*2+1];
                    float ox = (gv0 / (1.f + __expf(-gv0))) * uv0;
                    float oy = (gv1 / (1.f + __expf(-gv1))) * uv1;
                    *(uint32_t*)&g_actb[(size_t)(start + r)*FF + c] = pack_bf2(ox, oy);
                }
            }
        }
}

// =====================================================================
// MoE down GEMM (bf16 m16n8k16), 128x128 tile, double-buffered,
// float2-vectorized B fill. 8 warps: 4m x 2n. grid(DD/128, NSLOT/128, EE)
// =====================================================================
__global__ __launch_bounds__(256, 2)
void moe_down_bf16(const float* __restrict__ wd, float* __restrict__ out) {
    int e = blockIdx.z;
    int ne = g_counts[e];
    int rt = blockIdx.y*128;
    if (rt >= ne) return;
    int start = g_offsets[e];
    int n0 = blockIdx.x*128;

    __shared__ __nv_bfloat16 Ab[2][128*40];
    __shared__ uint32_t Bp[2][16*136];

    int tid = threadIdx.x;
    int lane = tid & 31, warp = tid >> 5;
    int m_w = (warp >> 1)*32, n_w = (warp & 1)*64;
    int g = lane >> 2, tg = lane & 3;
    int arow = tid >> 1, ah = tid & 1;

    uint32_t sA0 = (uint32_t)__cvta_generic_to_shared(&Ab[0][0]);
    uint32_t sA1 = (uint32_t)__cvta_generic_to_shared(&Ab[1][0]);
    const float* WD = wd + (size_t)e*FF*DD;

    float acc[2][8][4];
    #pragma unroll
    for (int i = 0; i < 2; i++)
        #pragma unroll
        for (int j = 0; j < 8; j++)
            #pragma unroll
            for (int l = 0; l < 4; l++) acc[i][j][l] = 0.f;

    int aslot;
    {
        int ar = start + rt + arow;
        aslot = (ar < NSLOT) ? ar : (NSLOT - 1);
    }

    uint4 av[2];
    float2 pb[4][2];   // [item][row]
    av[0] = *(const uint4*)&g_actb[(size_t)aslot*FF + ah*16];
    av[1] = *(const uint4*)&g_actb[(size_t)aslot*FF + ah*16 + 8];
    #pragma unroll
    for (int it2 = 0; it2 < 4; it2++) {
        int id = tid + it2*256;
        int kp = id >> 6, n = (id & 63)*2;
        size_t off = (size_t)(2*kp)*DD + n0 + n;
        pb[it2][0] = *(const float2*)&WD[off];
        pb[it2][1] = *(const float2*)&WD[off + DD];
    }
    *(uint4*)&Ab[0][arow*40 + ah*16]     = av[0];
    *(uint4*)&Ab[0][arow*40 + ah*16 + 8] = av[1];
    #pragma unroll
    for (int it2 = 0; it2 < 4; it2++) {
        int id = tid + it2*256;
        int kp = id >> 6, n = (id & 63)*2;
        uint2 v = make_uint2(pack_bf2(pb[it2][0].x, pb[it2][1].x),
                             pack_bf2(pb[it2][0].y, pb[it2][1].y));
        *(uint2*)&Bp[0][kp*136 + n] = v;
    }
    __syncthreads();

    const int NT = FF/32;
    for (int it = 0; it < NT; it++) {
        int cur = it & 1;
        if (it + 1 < NT) {
            int k0 = (it + 1)*32;
            av[0] = *(const uint4*)&g_actb[(size_t)aslot*FF + k0 + ah*16];
            av[1] = *(const uint4*)&g_actb[(size_t)aslot*FF + k0 + ah*16 + 8];
            #pragma unroll
            for (int it2 = 0; it2 < 4; it2++) {
                int id = tid + it2*256;
                int kp = id >> 6, n = (id & 63)*2;
                size_t off = (size_t)(k0 + 2*kp)*DD + n0 + n;
                pb[it2][0] = *(const float2*)&WD[off];
                pb[it2][1] = *(const float2*)&WD[off + DD];
            }
        }
        uint32_t sAb = cur ? sA1 : sA0;
        const uint32_t* BB = Bp[cur];
        #pragma unroll
        for (int ks = 0; ks < 2; ks++) {
            uint32_t a0[4], a1[4];
            uint32_t abyte = (uint32_t)(m_w + (lane & 15))*80u + (uint32_t)ks*32u + (lane & 16);
            ldsm4(a0, sAb + abyte);
            ldsm4(a1, sAb + abyte + 16u*80u);
            #pragma unroll
            for (int ni = 0; ni < 8; ni++) {
                int n = n_w + ni*8 + g;
                uint32_t b0 = BB[(ks*8 + tg)*136 + n];
                uint32_t b1 = BB[(ks*8 + tg + 4)*136 + n];
                mma16(acc[0][ni], a0, b0, b1);
                mma16(acc[1][ni], a1, b0, b1);
            }
        }
        if (it + 1 < NT) {
            int nxt = cur ^ 1;
            *(uint4*)&Ab[nxt][arow*40 + ah*16]     = av[0];
            *(uint4*)&Ab[nxt][arow*40 + ah*16 + 8] = av[1];
            #pragma unroll
            for (int it2 = 0; it2 < 4; it2++) {
                int id = tid + it2*256;
                int kp = id >> 6, n = (id & 63)*2;
                uint2 v = make_uint2(pack_bf2(pb[it2][0].x, pb[it2][1].x),
                                     pack_bf2(pb[it2][0].y, pb[it2][1].y));
                *(uint2*)&Bp[nxt][kp*136 + n] = v;
            }
        }
        __syncthreads();
    }

    #pragma unroll
    for (int mi = 0; mi < 2; mi++)
        #pragma unroll
        for (int ni = 0; ni < 8; ni++) {
            int rb = rt + m_w + mi*16 + g;
            int c = n0 + n_w + ni*8 + 2*tg;
            #pragma unroll
            for (int hrow = 0; hrow < 2; hrow++) {
                int r = rb + hrow*8;
                if (r < ne) {
                    int tok = g_slot_tok[start + r];
                    float w = g_slot_w[start + r];
                    atomicAdd(&out[(size_t)tok*DD + c],     w*acc[mi][ni][hrow*2]);
                    atomicAdd(&out[(size_t)tok*DD + c + 1], w*acc[mi][ni][hrow*2+1]);
                }
            }
        }
}

// ---------------- aux loss ----------------
__global__ void aux_kernel(float* __restrict__ out, int out_size) {
    if (threadIdx.x == 0 && out_size > TT*DD) {
        float aux = 0.f;
        for (int e = 0; e < EE; e++) {
            float frac = (float)g_counts[e] / (float)(TT*TOPK);
            float load = g_load[e] / (float)TT;
            aux += frac*load;
        }
        out[TT*DD] = LB * (float)EE * aux;
    }
}

// ---------------- launch ----------------
extern "C" void kernel_launch(void* const* d_in, const int* in_sizes, int n_in,
                              void* d_out, int out_size) {
    const float* x       = (const float*)d_in[0];
    const float* g1      = (const float*)d_in[1];
    const float* g2      = (const float*)d_in[2];
    const float* wq      = (const float*)d_in[3];
    const float* wk      = (const float*)d_in[4];
    const float* wv      = (const float*)d_in[5];
    const float* wo      = (const float*)d_in[6];
    const float* gate_w  = (const float*)d_in[7];
    const float* we_gate = (const float*)d_in[8];
    const float* we_up   = (const float*)d_in[9];
    const float* we_down = (const float*)d_in[10];
    float* out = (float*)d_out;

    static float *p_h = nullptr, *p_attn = nullptr;
    if (!p_h) {
        cudaGetSymbolAddress((void**)&p_h, g_h);
        cudaGetSymbolAddress((void**)&p_attn, g_attn);
        cudaFuncSetAttribute(attn_tf32_kernel, cudaFuncAttributeMaxDynamicSharedMemorySize,
                             ATTN_SMEM);
    }

    clear_kernel<<<1, 32>>>();
    rmsnorm_kernel<<<TT, 256>>>(x, g1, p_h);
    qkv_tf32_kernel<<<dim3(24, TT/128), 256>>>(wq, wk, wv);
    rope_kernel<<<512, 256>>>();
    attn_tf32_kernel<<<dim3(2*TT/64, HQ), 128, ATTN_SMEM>>>();
    attn_combine_kernel<<<TT, 256>>>();
    gemm_tf32_kernel<<<dim3(DD/64, TT/128), 256>>>(p_attn, wo, out, TT, DD, DD, x);
    rmsnorm_gate_kernel<<<TT, 256>>>(out, g2, gate_w);
    route_kernel<<<1, 1024>>>();
    moe_act_bf16<<<dim3(FF/64, NSLOT/128, EE), 256>>>(we_gate, we_up);
    moe_down_bf16<<<dim3(DD/128, NSLOT/128, EE), 256>>>(we_down, out);
    aux_kernel<<<1, 32>>>(out, out_size);
}